// round 1
// baseline (speedup 1.0000x reference)
#include <cuda_runtime.h>

#define BB 16
#define CIN 256
#define HH 32
#define WW 32
#define HW 1024
#define NHEAD 8
#define DHEAD 16
#define OQKV 384   // k(128) q(128) v(128)
#define DV 128

// Scratch (allocation-free): kqv activations and attention output (head-major channels)
__device__ float g_kqv[BB * OQKV * HW];   // [b][o][px]
__device__ float g_attn[BB * DV * HW];    // [b][nh*16+d][px]

// ---------------------------------------------------------------------------
// Kernel 1: QKV 1x1 conv.  kqv[b,o,px] = sum_c qkv_w[o,c]*x[b,c,px] + bias[o]
// (q rows pre-scaled by DKH^-0.5 = 0.25)
// Block: (px-tile 32, b). 256 thr: lane=px, warp owns 48 output channels.
// ---------------------------------------------------------------------------
#define SM_QKV ((32*36 + 384*32) * 4)
__global__ void __launch_bounds__(256, 2) k_qkv(const float* __restrict__ x,
                                                const float* __restrict__ w,
                                                const float* __restrict__ bias) {
    extern __shared__ float sm[];
    float* xs = sm;              // [32 px][36]  (transposed, padded)
    float* ws = sm + 32 * 36;    // [384 o][32 c]
    int b = blockIdx.y;
    int px0 = blockIdx.x * 32;
    int tid = threadIdx.x, lane = tid & 31, wid = tid >> 5;

    float acc[48];
#pragma unroll
    for (int i = 0; i < 48; i++) acc[i] = 0.f;

    const float* xb = x + ((size_t)b * CIN) * HW + px0;
    for (int c0 = 0; c0 < CIN; c0 += 32) {
        __syncthreads();
        for (int i = tid; i < 32 * 32; i += 256) {
            int c = i >> 5, p = i & 31;
            xs[p * 36 + c] = xb[(size_t)(c0 + c) * HW + p];
        }
        for (int i = tid; i < 384 * 32; i += 256) {
            int o = i >> 5, c = i & 31;
            ws[o * 32 + c] = w[(size_t)o * 256 + c0 + c];
        }
        __syncthreads();
#pragma unroll 2
        for (int c4 = 0; c4 < 32; c4 += 4) {
            float4 xv = *(const float4*)&xs[lane * 36 + c4];
#pragma unroll
            for (int oo = 0; oo < 48; oo++) {
                float4 wv = *(const float4*)&ws[(wid * 48 + oo) * 32 + c4];
                acc[oo] = fmaf(xv.x, wv.x, acc[oo]);
                acc[oo] = fmaf(xv.y, wv.y, acc[oo]);
                acc[oo] = fmaf(xv.z, wv.z, acc[oo]);
                acc[oo] = fmaf(xv.w, wv.w, acc[oo]);
            }
        }
    }
    float* outp = g_kqv + ((size_t)b * OQKV) * HW + px0 + lane;
#pragma unroll
    for (int oo = 0; oo < 48; oo++) {
        int o = wid * 48 + oo;
        float v = acc[oo] + bias[o];
        if (o >= 128 && o < 256) v *= 0.25f;   // q * DKH^-0.5
        outp[(size_t)o * HW] = v;
    }
}

// ---------------------------------------------------------------------------
// Kernel 2: 3x3 conv, SAME padding, NCHW x HWIO -> out channels [0,128)
// Block: (h, b). 256 thr: lane=w, warp owns 16 output channels.
// ---------------------------------------------------------------------------
#define SM_CONV ((16*3*34 + 9*16*128) * 4)
__global__ void __launch_bounds__(256, 2) k_conv(const float* __restrict__ x,
                                                 const float* __restrict__ w,
                                                 const float* __restrict__ bias,
                                                 float* __restrict__ out) {
    extern __shared__ float sm[];
    float* xs = sm;                  // [16 ci][3 kh][34 w+pad]
    float* ws = sm + 16 * 3 * 34;    // [9 p][16 ci][128 co]
    int b = blockIdx.y, h = blockIdx.x;
    int tid = threadIdx.x, lane = tid & 31, wid = tid >> 5;

    float acc[16];
#pragma unroll
    for (int i = 0; i < 16; i++) acc[i] = 0.f;

    for (int c0 = 0; c0 < CIN; c0 += 16) {
        __syncthreads();
        // input tile with halo + zero padding
        for (int i = tid; i < 16 * 102; i += 256) {
            int ci = i / 102;
            int rem = i - ci * 102;
            int kh = rem / 34;
            int wp = rem - kh * 34;
            int hy = h + kh - 1;
            int wx = wp - 1;
            float v = 0.f;
            if (hy >= 0 && hy < HH && wx >= 0 && wx < WW)
                v = x[(((size_t)b * CIN + c0 + ci) * HH + hy) * WW + wx];
            xs[i] = v;
        }
        // weight chunk [9][16][128]: co contiguous (HWIO)
        for (int i = tid * 4; i < 9 * 16 * 128; i += 1024) {
            int co = i & 127;
            int ci = (i >> 7) & 15;
            int p = i >> 11;
            *(float4*)&ws[i] = *(const float4*)&w[((size_t)p * 256 + c0 + ci) * 128 + co];
        }
        __syncthreads();
#pragma unroll 2
        for (int ci = 0; ci < 16; ci++) {
            float xv[9];
#pragma unroll
            for (int kh = 0; kh < 3; kh++)
#pragma unroll
                for (int kw = 0; kw < 3; kw++)
                    xv[kh * 3 + kw] = xs[(ci * 3 + kh) * 34 + lane + kw];
#pragma unroll
            for (int p = 0; p < 9; p++) {
                const float* wp = &ws[(p * 16 + ci) * 128 + wid * 16];
#pragma unroll
                for (int jj = 0; jj < 4; jj++) {
                    float4 wv = *(const float4*)&wp[jj * 4];
                    acc[jj * 4 + 0] = fmaf(xv[p], wv.x, acc[jj * 4 + 0]);
                    acc[jj * 4 + 1] = fmaf(xv[p], wv.y, acc[jj * 4 + 1]);
                    acc[jj * 4 + 2] = fmaf(xv[p], wv.z, acc[jj * 4 + 2]);
                    acc[jj * 4 + 3] = fmaf(xv[p], wv.w, acc[jj * 4 + 3]);
                }
            }
        }
    }
#pragma unroll
    for (int j = 0; j < 16; j++) {
        int co = wid * 16 + j;
        out[(((size_t)b * 256 + co) * HH + h) * WW + lane] = acc[j] + bias[co];
    }
}

// ---------------------------------------------------------------------------
// Kernel 3: attention. One block per (b, head). K/V transposed into smem
// (stride 20 words: 16B-aligned LDS.128, broadcast reads in mainloop).
// Single-pass softmax without max subtraction (logits bounded ~|4|).
// 512 threads, 2 query rows per thread.
// ---------------------------------------------------------------------------
#define SM_ATTN (2 * 1024 * 20 * 4)
__global__ void __launch_bounds__(512, 1) k_attn() {
    extern __shared__ float sm[];
    float* ksh = sm;               // [1024 j][20]
    float* vsh = sm + 1024 * 20;   // [1024 j][20]
    int bh = blockIdx.x;
    int b = bh >> 3, nh = bh & 7;
    int tid = threadIdx.x;

    const float* kg = g_kqv + ((size_t)b * OQKV + nh * 16) * HW;
    const float* qg = g_kqv + ((size_t)b * OQKV + 128 + nh * 16) * HW;
    const float* vg = g_kqv + ((size_t)b * OQKV + 256 + nh * 16) * HW;

    for (int i = tid; i < 16 * 1024; i += 512) {
        int d = i >> 10, j = i & 1023;
        float kv = kg[(size_t)d * HW + j];
        float vv = vg[(size_t)d * HW + j];
        ksh[j * 20 + d] = kv;
        vsh[j * 20 + d] = vv;
    }
    __syncthreads();

    float q[2][16], acc[2][16], se[2];
#pragma unroll
    for (int r = 0; r < 2; r++) {
        int row = r * 512 + tid;
        se[r] = 0.f;
#pragma unroll
        for (int d = 0; d < 16; d++) {
            q[r][d] = qg[(size_t)d * HW + row];
            acc[r][d] = 0.f;
        }
    }

#pragma unroll 2
    for (int j = 0; j < 1024; j++) {
        const float* kp = &ksh[j * 20];
        const float* vp = &vsh[j * 20];
        float4 k0 = *(const float4*)&kp[0];
        float4 k1 = *(const float4*)&kp[4];
        float4 k2 = *(const float4*)&kp[8];
        float4 k3 = *(const float4*)&kp[12];
        float4 v0 = *(const float4*)&vp[0];
        float4 v1 = *(const float4*)&vp[4];
        float4 v2 = *(const float4*)&vp[8];
        float4 v3 = *(const float4*)&vp[12];
#pragma unroll
        for (int r = 0; r < 2; r++) {
            // 4 parallel partial dot chains (latency ~24 cyc instead of 64)
            float p0 = q[r][0] * k0.x;
            p0 = fmaf(q[r][1], k0.y, p0);
            p0 = fmaf(q[r][2], k0.z, p0);
            p0 = fmaf(q[r][3], k0.w, p0);
            float p1 = q[r][4] * k1.x;
            p1 = fmaf(q[r][5], k1.y, p1);
            p1 = fmaf(q[r][6], k1.z, p1);
            p1 = fmaf(q[r][7], k1.w, p1);
            float p2 = q[r][8] * k2.x;
            p2 = fmaf(q[r][9], k2.y, p2);
            p2 = fmaf(q[r][10], k2.z, p2);
            p2 = fmaf(q[r][11], k2.w, p2);
            float p3 = q[r][12] * k3.x;
            p3 = fmaf(q[r][13], k3.y, p3);
            p3 = fmaf(q[r][14], k3.z, p3);
            p3 = fmaf(q[r][15], k3.w, p3);
            float s = (p0 + p1) + (p2 + p3);
            float e = __expf(s);
            se[r] += e;
            acc[r][0]  = fmaf(e, v0.x, acc[r][0]);
            acc[r][1]  = fmaf(e, v0.y, acc[r][1]);
            acc[r][2]  = fmaf(e, v0.z, acc[r][2]);
            acc[r][3]  = fmaf(e, v0.w, acc[r][3]);
            acc[r][4]  = fmaf(e, v1.x, acc[r][4]);
            acc[r][5]  = fmaf(e, v1.y, acc[r][5]);
            acc[r][6]  = fmaf(e, v1.z, acc[r][6]);
            acc[r][7]  = fmaf(e, v1.w, acc[r][7]);
            acc[r][8]  = fmaf(e, v2.x, acc[r][8]);
            acc[r][9]  = fmaf(e, v2.y, acc[r][9]);
            acc[r][10] = fmaf(e, v2.z, acc[r][10]);
            acc[r][11] = fmaf(e, v2.w, acc[r][11]);
            acc[r][12] = fmaf(e, v3.x, acc[r][12]);
            acc[r][13] = fmaf(e, v3.y, acc[r][13]);
            acc[r][14] = fmaf(e, v3.z, acc[r][14]);
            acc[r][15] = fmaf(e, v3.w, acc[r][15]);
        }
    }

    float* outp = g_attn + ((size_t)b * DV + nh * 16) * HW;
#pragma unroll
    for (int r = 0; r < 2; r++) {
        int row = r * 512 + tid;
        float inv = 1.0f / se[r];
#pragma unroll
        for (int d = 0; d < 16; d++)
            outp[(size_t)d * HW + row] = acc[r][d] * inv;
    }
}

// ---------------------------------------------------------------------------
// Kernel 4: 1x1 output projection -> out channels [128,256)
// ---------------------------------------------------------------------------
#define SM_PROJ ((32*132 + 128*128) * 4)
__global__ void __launch_bounds__(256, 2) k_proj(const float* __restrict__ pw,
                                                 const float* __restrict__ pb,
                                                 float* __restrict__ out) {
    extern __shared__ float sm[];
    float* xs = sm;               // [32 px][132]
    float* ws = sm + 32 * 132;    // [128 o][128 c]
    int b = blockIdx.y;
    int px0 = blockIdx.x * 32;
    int tid = threadIdx.x, lane = tid & 31, wid = tid >> 5;

    float acc[16];
#pragma unroll
    for (int i = 0; i < 16; i++) acc[i] = 0.f;

    for (int i = tid * 4; i < 128 * 128; i += 1024)
        *(float4*)&ws[i] = *(const float4*)&pw[i];
    for (int i = tid; i < 32 * 128; i += 256) {
        int c = i >> 5, p = i & 31;
        xs[p * 132 + c] = g_attn[((size_t)b * DV + c) * HW + px0 + p];
    }
    __syncthreads();

#pragma unroll 4
    for (int c4 = 0; c4 < 128; c4 += 4) {
        float4 xv = *(const float4*)&xs[lane * 132 + c4];
#pragma unroll
        for (int oo = 0; oo < 16; oo++) {
            float4 wv = *(const float4*)&ws[(wid * 16 + oo) * 128 + c4];
            acc[oo] = fmaf(xv.x, wv.x, acc[oo]);
            acc[oo] = fmaf(xv.y, wv.y, acc[oo]);
            acc[oo] = fmaf(xv.z, wv.z, acc[oo]);
            acc[oo] = fmaf(xv.w, wv.w, acc[oo]);
        }
    }
#pragma unroll
    for (int oo = 0; oo < 16; oo++) {
        int co = wid * 16 + oo;
        out[(((size_t)b * 256 + 128 + co) * HW) + px0 + lane] = acc[oo] + pb[co];
    }
}

// ---------------------------------------------------------------------------
extern "C" void kernel_launch(void* const* d_in, const int* in_sizes, int n_in,
                              void* d_out, int out_size) {
    const float* x      = (const float*)d_in[0];
    const float* conv_w = (const float*)d_in[1];
    const float* conv_b = (const float*)d_in[2];
    const float* qkv_w  = (const float*)d_in[3];
    const float* qkv_b  = (const float*)d_in[4];
    const float* proj_w = (const float*)d_in[5];
    const float* proj_b = (const float*)d_in[6];
    float* out = (float*)d_out;

    cudaFuncSetAttribute(k_qkv,  cudaFuncAttributeMaxDynamicSharedMemorySize, SM_QKV);
    cudaFuncSetAttribute(k_conv, cudaFuncAttributeMaxDynamicSharedMemorySize, SM_CONV);
    cudaFuncSetAttribute(k_attn, cudaFuncAttributeMaxDynamicSharedMemorySize, SM_ATTN);
    cudaFuncSetAttribute(k_proj, cudaFuncAttributeMaxDynamicSharedMemorySize, SM_PROJ);

    k_qkv<<<dim3(32, 16), 256, SM_QKV>>>(x, qkv_w, qkv_b);
    k_conv<<<dim3(32, 16), 256, SM_CONV>>>(x, conv_w, conv_b, out);
    k_attn<<<BB * NHEAD, 512, SM_ATTN>>>();
    k_proj<<<dim3(32, 16), 256, SM_PROJ>>>(proj_w, proj_b, out);
}

// round 2
// speedup vs baseline: 6.4155x; 6.4155x over previous
#include <cuda_runtime.h>
#include <cuda_fp16.h>

#define HH 32
#define WW 32
#define HW 1024
#define NB 16

// ---------------- scratch (allocation-free) ----------------
__device__ __half g_xh[NB * 1024 * 256];     // x transposed [b][px][c]
__device__ __half g_wqkvh[384 * 256];        // [o][c]
__device__ __half g_wconvh[128 * 9 * 256];   // [co][p*256+ci]
__device__ __half g_wprojh[128 * 128];       // [o][c]
__device__ __half g_kT[NB * 1024 * 128];     // [b][px][d]
__device__ __half g_qT[NB * 1024 * 128];     // [b][px][d]
__device__ __half g_v[NB * 128 * 1024];      // [b][d][px]
__device__ __half g_ah[NB * 1024 * 128];     // attn out [b][px][c]

// ---------------- helpers ----------------
__device__ __forceinline__ void mma16816(float c[4], const unsigned a[4], const unsigned b[2]) {
    asm volatile(
        "mma.sync.aligned.m16n8k16.row.col.f32.f16.f16.f32 "
        "{%0,%1,%2,%3}, {%4,%5,%6,%7}, {%8,%9}, {%0,%1,%2,%3};\n"
        : "+f"(c[0]), "+f"(c[1]), "+f"(c[2]), "+f"(c[3])
        : "r"(a[0]), "r"(a[1]), "r"(a[2]), "r"(a[3]), "r"(b[0]), "r"(b[1]));
}
__device__ __forceinline__ unsigned ldu32(const __half* p) {
    return *reinterpret_cast<const unsigned*>(p);
}
__device__ __forceinline__ unsigned packh2(float a, float b) {
    __half2 h = __floats2half2_rn(a, b);
    return *reinterpret_cast<unsigned*>(&h);
}

// ---------------- conversion kernels ----------------
// x [b][c][px] fp32 -> g_xh [b][px][c] fp16 (32x32 smem transpose)
__global__ void k_cvt_x(const float* __restrict__ x) {
    __shared__ float t[32][33];
    int b = blockIdx.z, c0 = blockIdx.y * 32, px0 = blockIdx.x * 32;
    int tx = threadIdx.x, ty = threadIdx.y;
#pragma unroll
    for (int yy = 0; yy < 4; yy++)
        t[ty + yy * 8][tx] = x[((size_t)b * 256 + c0 + ty + yy * 8) * HW + px0 + tx];
    __syncthreads();
#pragma unroll
    for (int yy = 0; yy < 4; yy++)
        g_xh[((size_t)b * 1024 + px0 + ty + yy * 8) * 256 + c0 + tx] =
            __float2half(t[tx][ty + yy * 8]);
}

// weights: qkv straight, proj straight, conv transposed [k][co] -> [co][k]
__global__ void k_cvt_w(const float* __restrict__ qkv_w,
                        const float* __restrict__ proj_w,
                        const float* __restrict__ conv_w) {
    int i = blockIdx.x * 256 + threadIdx.x;
    if (i < 384 * 256) g_wqkvh[i] = __float2half(qkv_w[i]);
    if (i < 128 * 128) g_wprojh[i] = __float2half(proj_w[i]);
    if (i < 128 * 2304) {
        int co = i / 2304;
        int k = i - co * 2304;
        g_wconvh[i] = __float2half(conv_w[(size_t)k * 128 + co]);
    }
}

// ---------------- kernel 1: QKV GEMM (M=384, N=1024, K=256 per batch) ----------------
// grid (8 n-tiles, 3 m-tiles, 16 b), 256 thr; block tile 128x128; warp tile 64x32
__global__ void __launch_bounds__(256) k_qkv(const float* __restrict__ bias) {
    __shared__ __half As[128 * 72];
    __shared__ __half Bs[128 * 72];
    int b = blockIdx.z, mt = blockIdx.y;
    int m0 = mt * 128, px0 = blockIdx.x * 128;
    int tid = threadIdx.x, lane = tid & 31, wid = tid >> 5;
    int wm = wid >> 2, wn = wid & 3;
    int g = lane >> 2, t = lane & 3;

    float acc[4][4][4];
#pragma unroll
    for (int i = 0; i < 4; i++)
#pragma unroll
        for (int j = 0; j < 4; j++)
#pragma unroll
            for (int k = 0; k < 4; k++) acc[i][j][k] = 0.f;

    for (int ph = 0; ph < 4; ph++) {
        int kc0 = ph * 64;
        __syncthreads();
#pragma unroll
        for (int i = tid; i < 128 * 8; i += 256) {
            int r = i >> 3, ch = i & 7;
            *(uint4*)&As[r * 72 + ch * 8] =
                *(const uint4*)&g_wqkvh[(size_t)(m0 + r) * 256 + kc0 + ch * 8];
            *(uint4*)&Bs[r * 72 + ch * 8] =
                *(const uint4*)&g_xh[((size_t)b * 1024 + px0 + r) * 256 + kc0 + ch * 8];
        }
        __syncthreads();
#pragma unroll
        for (int ks = 0; ks < 4; ks++) {
            unsigned af[4][4], bf[4][2];
#pragma unroll
            for (int mi = 0; mi < 4; mi++) {
                int base = (wm * 64 + mi * 16 + g) * 72 + ks * 16 + 2 * t;
                af[mi][0] = ldu32(&As[base]);
                af[mi][1] = ldu32(&As[base + 8 * 72]);
                af[mi][2] = ldu32(&As[base + 8]);
                af[mi][3] = ldu32(&As[base + 8 * 72 + 8]);
            }
#pragma unroll
            for (int ni = 0; ni < 4; ni++) {
                int bb = (wn * 32 + ni * 8 + g) * 72 + ks * 16 + 2 * t;
                bf[ni][0] = ldu32(&Bs[bb]);
                bf[ni][1] = ldu32(&Bs[bb + 8]);
            }
#pragma unroll
            for (int mi = 0; mi < 4; mi++)
#pragma unroll
                for (int ni = 0; ni < 4; ni++) mma16816(acc[mi][ni], af[mi], bf[ni]);
        }
    }

    float scale = (mt == 1) ? 0.25f : 1.0f;
#pragma unroll
    for (int mi = 0; mi < 4; mi++) {
        int r0 = wm * 64 + mi * 16 + g;
        float b0v = bias[m0 + r0], b1v = bias[m0 + r0 + 8];
#pragma unroll
        for (int ni = 0; ni < 4; ni++) {
            int px = px0 + wn * 32 + ni * 8 + 2 * t;
            float v0 = (acc[mi][ni][0] + b0v) * scale;
            float v1 = (acc[mi][ni][1] + b0v) * scale;
            float v2 = (acc[mi][ni][2] + b1v) * scale;
            float v3 = (acc[mi][ni][3] + b1v) * scale;
            if (mt == 2) {
                *reinterpret_cast<__half2*>(&g_v[((size_t)b * 128 + r0) * 1024 + px]) =
                    __floats2half2_rn(v0, v1);
                *reinterpret_cast<__half2*>(&g_v[((size_t)b * 128 + r0 + 8) * 1024 + px]) =
                    __floats2half2_rn(v2, v3);
            } else {
                __half* base = (mt == 0 ? g_kT : g_qT) + ((size_t)b * 1024 + px) * 128;
                base[r0] = __float2half(v0);
                base[r0 + 8] = __float2half(v2);
                base[128 + r0] = __float2half(v1);
                base[128 + r0 + 8] = __float2half(v3);
            }
        }
    }
}

// ---------------- kernel 2: conv implicit GEMM (M=128 co, N=1024 px, K=9*256) ----------------
// grid (16 n-tiles, 16 b), 256 thr; block tile 128x64; warp tile 32x32
__global__ void __launch_bounds__(256) k_conv(const float* __restrict__ conv_b,
                                              float* __restrict__ out) {
    __shared__ __half As[128 * 72];
    __shared__ __half Bs[64 * 72];
    int b = blockIdx.y;
    int px0 = blockIdx.x * 64;
    int tid = threadIdx.x, lane = tid & 31, wid = tid >> 5;
    int wm = wid >> 1, wn = wid & 1;
    int g = lane >> 2, t = lane & 3;

    float acc[2][4][4];
#pragma unroll
    for (int i = 0; i < 2; i++)
#pragma unroll
        for (int j = 0; j < 4; j++)
#pragma unroll
            for (int k = 0; k < 4; k++) acc[i][j][k] = 0.f;

    for (int p = 0; p < 9; p++) {
        int dh = p / 3 - 1, dw = p % 3 - 1;
        for (int cq = 0; cq < 4; cq++) {
            int kc0 = cq * 64;
            __syncthreads();
            // A: weights [128 co][64 k]
#pragma unroll
            for (int i = tid; i < 128 * 8; i += 256) {
                int r = i >> 3, ch = i & 7;
                *(uint4*)&As[r * 72 + ch * 8] =
                    *(const uint4*)&g_wconvh[(size_t)r * 2304 + p * 256 + kc0 + ch * 8];
            }
            // B: shifted x [64 px][64 ci]
#pragma unroll
            for (int i = tid; i < 64 * 8; i += 256) {
                int r = i >> 3, ch = i & 7;
                int px = px0 + r;
                int hy = (px >> 5) + dh, wx = (px & 31) + dw;
                uint4 val = make_uint4(0, 0, 0, 0);
                if (hy >= 0 && hy < HH && wx >= 0 && wx < WW)
                    val = *(const uint4*)&g_xh[((size_t)b * 1024 + hy * 32 + wx) * 256 +
                                               kc0 + ch * 8];
                *(uint4*)&Bs[r * 72 + ch * 8] = val;
            }
            __syncthreads();
#pragma unroll
            for (int ks = 0; ks < 4; ks++) {
                unsigned af[2][4], bf[4][2];
#pragma unroll
                for (int mi = 0; mi < 2; mi++) {
                    int base = (wm * 32 + mi * 16 + g) * 72 + ks * 16 + 2 * t;
                    af[mi][0] = ldu32(&As[base]);
                    af[mi][1] = ldu32(&As[base + 8 * 72]);
                    af[mi][2] = ldu32(&As[base + 8]);
                    af[mi][3] = ldu32(&As[base + 8 * 72 + 8]);
                }
#pragma unroll
                for (int ni = 0; ni < 4; ni++) {
                    int bb = (wn * 32 + ni * 8 + g) * 72 + ks * 16 + 2 * t;
                    bf[ni][0] = ldu32(&Bs[bb]);
                    bf[ni][1] = ldu32(&Bs[bb + 8]);
                }
#pragma unroll
                for (int mi = 0; mi < 2; mi++)
#pragma unroll
                    for (int ni = 0; ni < 4; ni++) mma16816(acc[mi][ni], af[mi], bf[ni]);
            }
        }
    }

#pragma unroll
    for (int mi = 0; mi < 2; mi++) {
        int r0 = wm * 32 + mi * 16 + g;
        float b0v = conv_b[r0], b1v = conv_b[r0 + 8];
#pragma unroll
        for (int ni = 0; ni < 4; ni++) {
            int px = px0 + wn * 32 + ni * 8 + 2 * t;
            *(float2*)&out[((size_t)b * 256 + r0) * 1024 + px] =
                make_float2(acc[mi][ni][0] + b0v, acc[mi][ni][1] + b0v);
            *(float2*)&out[((size_t)b * 256 + r0 + 8) * 1024 + px] =
                make_float2(acc[mi][ni][2] + b1v, acc[mi][ni][3] + b1v);
        }
    }
}

// ---------------- kernel 3: attention ----------------
// grid (4 i-tiles, 8 heads, 16 b), 256 thr; warp = 32 query rows; j-chunks of 32
__global__ void __launch_bounds__(256, 2) k_attn() {
    extern __shared__ __half sm[];
    __half* ksh = sm;                 // [1024 j][24]  (d in cols 0..15)
    __half* vsh = sm + 1024 * 24;     // [16 d][1032 j]
    int b = blockIdx.z, h = blockIdx.y;
    int i0 = blockIdx.x * 256;
    int tid = threadIdx.x, lane = tid & 31, wid = tid >> 5;
    int g = lane >> 2, t = lane & 3;

    // load K: g_kT[b][j][h*16 .. +16) -> ksh[j][0..16)
    {
        const __half* kg = g_kT + (size_t)b * 1024 * 128 + h * 16;
#pragma unroll
        for (int i = tid; i < 2048; i += 256) {
            int j = i >> 1, ch = i & 1;
            *(uint4*)&ksh[j * 24 + ch * 8] = *(const uint4*)&kg[(size_t)j * 128 + ch * 8];
        }
    }
    // load V: g_v[b][h*16+d][j] -> vsh[d][j]
    {
        const __half* vg = g_v + ((size_t)b * 128 + h * 16) * 1024;
#pragma unroll
        for (int i = tid; i < 2048; i += 256) {
            int d = i >> 7, jc = i & 127;
            *(uint4*)&vsh[d * 1032 + jc * 8] = *(const uint4*)&vg[(size_t)d * 1024 + jc * 8];
        }
    }

    // Q fragments (persistent)
    unsigned qa[2][4];
    {
        const __half* qg = g_qT + ((size_t)b * 1024 + i0 + wid * 32) * 128 + h * 16;
#pragma unroll
        for (int mi = 0; mi < 2; mi++) {
            qa[mi][0] = ldu32(&qg[(size_t)(mi * 16 + g) * 128 + 2 * t]);
            qa[mi][1] = ldu32(&qg[(size_t)(mi * 16 + g + 8) * 128 + 2 * t]);
            qa[mi][2] = ldu32(&qg[(size_t)(mi * 16 + g) * 128 + 2 * t + 8]);
            qa[mi][3] = ldu32(&qg[(size_t)(mi * 16 + g + 8) * 128 + 2 * t + 8]);
        }
    }
    __syncthreads();

    float oacc[2][2][4];
#pragma unroll
    for (int i = 0; i < 2; i++)
#pragma unroll
        for (int j = 0; j < 2; j++)
#pragma unroll
            for (int k = 0; k < 4; k++) oacc[i][j][k] = 0.f;
    float rs[2][2] = {{0.f, 0.f}, {0.f, 0.f}};

    for (int jc = 0; jc < 32; jc++) {
        int j0 = jc * 32;
        unsigned kb[4][2];
#pragma unroll
        for (int ni = 0; ni < 4; ni++) {
            int j = j0 + ni * 8 + g;
            kb[ni][0] = ldu32(&ksh[j * 24 + 2 * t]);
            kb[ni][1] = ldu32(&ksh[j * 24 + 2 * t + 8]);
        }
        float s[2][4][4];
#pragma unroll
        for (int mi = 0; mi < 2; mi++)
#pragma unroll
            for (int ni = 0; ni < 4; ni++) {
#pragma unroll
                for (int k = 0; k < 4; k++) s[mi][ni][k] = 0.f;
                mma16816(s[mi][ni], qa[mi], kb[ni]);
            }
        // exp + rowsum + pack to fp16 A-fragments for PV
        unsigned pf[2][4][2];
#pragma unroll
        for (int mi = 0; mi < 2; mi++)
#pragma unroll
            for (int ni = 0; ni < 4; ni++) {
                float e0 = __expf(s[mi][ni][0]);
                float e1 = __expf(s[mi][ni][1]);
                float e2 = __expf(s[mi][ni][2]);
                float e3 = __expf(s[mi][ni][3]);
                rs[mi][0] += e0 + e1;
                rs[mi][1] += e2 + e3;
                pf[mi][ni][0] = packh2(e0, e1);
                pf[mi][ni][1] = packh2(e2, e3);
            }
        // PV: 2 k16-steps over the 32 j's
#pragma unroll
        for (int ks = 0; ks < 2; ks++) {
            unsigned av[2][4];
#pragma unroll
            for (int mi = 0; mi < 2; mi++) {
                av[mi][0] = pf[mi][2 * ks][0];
                av[mi][1] = pf[mi][2 * ks][1];
                av[mi][2] = pf[mi][2 * ks + 1][0];
                av[mi][3] = pf[mi][2 * ks + 1][1];
            }
#pragma unroll
            for (int nd = 0; nd < 2; nd++) {
                unsigned vb[2];
                vb[0] = ldu32(&vsh[(nd * 8 + g) * 1032 + j0 + ks * 16 + 2 * t]);
                vb[1] = ldu32(&vsh[(nd * 8 + g) * 1032 + j0 + ks * 16 + 2 * t + 8]);
#pragma unroll
                for (int mi = 0; mi < 2; mi++) mma16816(oacc[mi][nd], av[mi], vb);
            }
        }
    }

    // reduce rowsums across the 4 lanes sharing a row (t = lane&3)
#pragma unroll
    for (int mi = 0; mi < 2; mi++)
#pragma unroll
        for (int half = 0; half < 2; half++) {
            float v = rs[mi][half];
            v += __shfl_xor_sync(0xffffffffu, v, 1);
            v += __shfl_xor_sync(0xffffffffu, v, 2);
            rs[mi][half] = 1.0f / v;
        }

    // write O (fp16, [b][px][c]) normalized
    __half* og = g_ah + ((size_t)b * 1024 + i0 + wid * 32) * 128 + h * 16;
#pragma unroll
    for (int mi = 0; mi < 2; mi++)
#pragma unroll
        for (int nd = 0; nd < 2; nd++) {
            int col = nd * 8 + 2 * t;
            *reinterpret_cast<__half2*>(&og[(size_t)(mi * 16 + g) * 128 + col]) =
                __floats2half2_rn(oacc[mi][nd][0] * rs[mi][0], oacc[mi][nd][1] * rs[mi][0]);
            *reinterpret_cast<__half2*>(&og[(size_t)(mi * 16 + g + 8) * 128 + col]) =
                __floats2half2_rn(oacc[mi][nd][2] * rs[mi][1], oacc[mi][nd][3] * rs[mi][1]);
        }
}

// ---------------- kernel 4: proj GEMM (M=128, N=1024, K=128) ----------------
// grid (16 n-tiles, 16 b), 256 thr; block tile 128x64; warp 32x32
__global__ void __launch_bounds__(256) k_proj(const float* __restrict__ proj_b,
                                              float* __restrict__ out) {
    __shared__ __half As[128 * 72];
    __shared__ __half Bs[64 * 72];
    int b = blockIdx.y;
    int px0 = blockIdx.x * 64;
    int tid = threadIdx.x, lane = tid & 31, wid = tid >> 5;
    int wm = wid >> 1, wn = wid & 1;
    int g = lane >> 2, t = lane & 3;

    float acc[2][4][4];
#pragma unroll
    for (int i = 0; i < 2; i++)
#pragma unroll
        for (int j = 0; j < 4; j++)
#pragma unroll
            for (int k = 0; k < 4; k++) acc[i][j][k] = 0.f;

    for (int ph = 0; ph < 2; ph++) {
        int kc0 = ph * 64;
        __syncthreads();
#pragma unroll
        for (int i = tid; i < 128 * 8; i += 256) {
            int r = i >> 3, ch = i & 7;
            *(uint4*)&As[r * 72 + ch * 8] =
                *(const uint4*)&g_wprojh[(size_t)r * 128 + kc0 + ch * 8];
        }
#pragma unroll
        for (int i = tid; i < 64 * 8; i += 256) {
            int r = i >> 3, ch = i & 7;
            *(uint4*)&Bs[r * 72 + ch * 8] =
                *(const uint4*)&g_ah[((size_t)b * 1024 + px0 + r) * 128 + kc0 + ch * 8];
        }
        __syncthreads();
#pragma unroll
        for (int ks = 0; ks < 4; ks++) {
            unsigned af[2][4], bf[4][2];
#pragma unroll
            for (int mi = 0; mi < 2; mi++) {
                int base = (wm * 32 + mi * 16 + g) * 72 + ks * 16 + 2 * t;
                af[mi][0] = ldu32(&As[base]);
                af[mi][1] = ldu32(&As[base + 8 * 72]);
                af[mi][2] = ldu32(&As[base + 8]);
                af[mi][3] = ldu32(&As[base + 8 * 72 + 8]);
            }
#pragma unroll
            for (int ni = 0; ni < 4; ni++) {
                int bb = (wn * 32 + ni * 8 + g) * 72 + ks * 16 + 2 * t;
                bf[ni][0] = ldu32(&Bs[bb]);
                bf[ni][1] = ldu32(&Bs[bb + 8]);
            }
#pragma unroll
            for (int mi = 0; mi < 2; mi++)
#pragma unroll
                for (int ni = 0; ni < 4; ni++) mma16816(acc[mi][ni], af[mi], bf[ni]);
        }
    }

#pragma unroll
    for (int mi = 0; mi < 2; mi++) {
        int r0 = wm * 32 + mi * 16 + g;
        float b0v = proj_b[r0], b1v = proj_b[r0 + 8];
#pragma unroll
        for (int ni = 0; ni < 4; ni++) {
            int px = px0 + wn * 32 + ni * 8 + 2 * t;
            *(float2*)&out[((size_t)b * 256 + 128 + r0) * 1024 + px] =
                make_float2(acc[mi][ni][0] + b0v, acc[mi][ni][1] + b0v);
            *(float2*)&out[((size_t)b * 256 + 128 + r0 + 8) * 1024 + px] =
                make_float2(acc[mi][ni][2] + b1v, acc[mi][ni][3] + b1v);
        }
    }
}

// ---------------------------------------------------------------------------
extern "C" void kernel_launch(void* const* d_in, const int* in_sizes, int n_in,
                              void* d_out, int out_size) {
    const float* x      = (const float*)d_in[0];
    const float* conv_w = (const float*)d_in[1];
    const float* conv_b = (const float*)d_in[2];
    const float* qkv_w  = (const float*)d_in[3];
    const float* qkv_b  = (const float*)d_in[4];
    const float* proj_w = (const float*)d_in[5];
    const float* proj_b = (const float*)d_in[6];
    float* out = (float*)d_out;

    static const int ATTN_SMEM = (1024 * 24 + 16 * 1032) * 2;  // 82176 B
    cudaFuncSetAttribute(k_attn, cudaFuncAttributeMaxDynamicSharedMemorySize, ATTN_SMEM);

    k_cvt_x<<<dim3(32, 8, NB), dim3(32, 8)>>>(x);
    k_cvt_w<<<1152, 256>>>(qkv_w, proj_w, conv_w);
    k_qkv<<<dim3(8, 3, NB), 256>>>(qkv_b);
    k_conv<<<dim3(16, NB), 256>>>(conv_b, out);
    k_attn<<<dim3(4, 8, NB), 256, ATTN_SMEM>>>();
    k_proj<<<dim3(16, NB), 256>>>(proj_b, out);
}

// round 3
// speedup vs baseline: 8.0299x; 1.2516x over previous
#include <cuda_runtime.h>
#include <cuda_fp16.h>
#include <cstdint>

#define HH 32
#define WW 32
#define HW 1024
#define NB 16

// ---------------- scratch (allocation-free) ----------------
__device__ __half g_xh[NB * 1024 * 256];     // x transposed [b][px][c]
__device__ __half g_wqkvh[384 * 256];        // [o][c]
__device__ __half g_wconvh[128 * 9 * 256];   // [co][p*256+ci]
__device__ __half g_wprojh[128 * 128];       // [o][c]
__device__ __half g_kT[NB * 1024 * 128];     // [b][px][d]
__device__ __half g_qT[NB * 1024 * 128];     // [b][px][d] (pre-scaled by 0.25*log2e)
__device__ __half g_v[NB * 128 * 1024];      // [b][d][px]
__device__ __half g_ah[NB * 1024 * 128];     // attn out [b][px][c]

// ---------------- helpers ----------------
__device__ __forceinline__ void mma16816(float c[4], const unsigned a[4], const unsigned b[2]) {
    asm volatile(
        "mma.sync.aligned.m16n8k16.row.col.f32.f16.f16.f32 "
        "{%0,%1,%2,%3}, {%4,%5,%6,%7}, {%8,%9}, {%0,%1,%2,%3};\n"
        : "+f"(c[0]), "+f"(c[1]), "+f"(c[2]), "+f"(c[3])
        : "r"(a[0]), "r"(a[1]), "r"(a[2]), "r"(a[3]), "r"(b[0]), "r"(b[1]));
}
__device__ __forceinline__ void ldsm4(unsigned& r0, unsigned& r1, unsigned& r2, unsigned& r3,
                                      const __half* p) {
    uint32_t a = (uint32_t)__cvta_generic_to_shared(p);
    asm volatile("ldmatrix.sync.aligned.m8n8.x4.shared.b16 {%0,%1,%2,%3},[%4];\n"
                 : "=r"(r0), "=r"(r1), "=r"(r2), "=r"(r3) : "r"(a));
}
__device__ __forceinline__ unsigned ldu32(const __half* p) {
    return *reinterpret_cast<const unsigned*>(p);
}
__device__ __forceinline__ unsigned packh2(float a, float b) {
    __half2 h = __floats2half2_rn(a, b);
    return *reinterpret_cast<unsigned*>(&h);
}
__device__ __forceinline__ unsigned ex2h2(unsigned x) {
    unsigned d;
    asm("ex2.approx.f16x2 %0,%1;" : "=r"(d) : "r"(x));
    return d;
}
__device__ __forceinline__ void cpa16(const __half* dst, const __half* src) {
    uint32_t d = (uint32_t)__cvta_generic_to_shared(dst);
    asm volatile("cp.async.cg.shared.global [%0],[%1],16;\n" :: "r"(d), "l"(src));
}
__device__ __forceinline__ void cpa16z(const __half* dst, const __half* src, bool ok) {
    uint32_t d = (uint32_t)__cvta_generic_to_shared(dst);
    int sz = ok ? 16 : 0;
    asm volatile("cp.async.cg.shared.global [%0],[%1],16,%2;\n" :: "r"(d), "l"(src), "r"(sz));
}
#define CP_COMMIT() asm volatile("cp.async.commit_group;\n" ::: "memory")
#define CP_WAIT(n)  asm volatile("cp.async.wait_group %0;\n" :: "n"(n) : "memory")

// Generic MMA tile: A [.. x K] rows stride STR, B [n x K] rows stride STR (both K-major).
template <int MI, int NI, int KSTEPS, int STR>
__device__ __forceinline__ void mma_tile(const __half* As, const __half* Bs, int arow0,
                                         int brow0, int lane, float (&acc)[MI][NI][4]) {
    int l7 = lane & 7, s1 = (lane >> 3) & 1, s2 = lane >> 4;
#pragma unroll
    for (int ks = 0; ks < KSTEPS; ks++) {
        unsigned af[MI][4], bf[NI][2];
#pragma unroll
        for (int mi = 0; mi < MI; mi++)
            ldsm4(af[mi][0], af[mi][1], af[mi][2], af[mi][3],
                  &As[(arow0 + mi * 16 + s1 * 8 + l7) * STR + ks * 16 + s2 * 8]);
#pragma unroll
        for (int np = 0; np < NI / 2; np++)
            ldsm4(bf[2 * np][0], bf[2 * np][1], bf[2 * np + 1][0], bf[2 * np + 1][1],
                  &Bs[(brow0 + np * 16 + s2 * 8 + l7) * STR + ks * 16 + s1 * 8]);
#pragma unroll
        for (int mi = 0; mi < MI; mi++)
#pragma unroll
            for (int ni = 0; ni < NI; ni++) mma16816(acc[mi][ni], af[mi], bf[ni]);
    }
}

// ---------------- conversion kernels ----------------
__global__ void k_cvt_x(const float* __restrict__ x) {
    __shared__ float t[32][33];
    int b = blockIdx.z, c0 = blockIdx.y * 32, px0 = blockIdx.x * 32;
    int tx = threadIdx.x, ty = threadIdx.y;
#pragma unroll
    for (int yy = 0; yy < 4; yy++)
        t[ty + yy * 8][tx] = x[((size_t)b * 256 + c0 + ty + yy * 8) * HW + px0 + tx];
    __syncthreads();
#pragma unroll
    for (int yy = 0; yy < 4; yy++)
        g_xh[((size_t)b * 1024 + px0 + ty + yy * 8) * 256 + c0 + tx] =
            __float2half(t[tx][ty + yy * 8]);
}

__global__ void k_cvt_w(const float* __restrict__ qkv_w,
                        const float* __restrict__ proj_w,
                        const float* __restrict__ conv_w) {
    int i = blockIdx.x * 256 + threadIdx.x;
    if (i < 384 * 256) g_wqkvh[i] = __float2half(qkv_w[i]);
    if (i < 128 * 128) g_wprojh[i] = __float2half(proj_w[i]);
    if (i < 128 * 2304) {
        int co = i / 2304;
        int k = i - co * 2304;
        g_wconvh[i] = __float2half(conv_w[(size_t)k * 128 + co]);
    }
}

// ---------------- kernel 1: QKV GEMM (M=384, N=1024, K=256 per batch) ----------------
// block tile 128x128, 256 thr, warp 64x32; cp.async double buffer over 4 K-phases
__global__ void __launch_bounds__(256) k_qkv(const float* __restrict__ bias) {
    extern __shared__ __half dsm[];
    __half* Asb[2] = {dsm, dsm + 18432};
    __half* Bsb[2] = {dsm + 9216, dsm + 18432 + 9216};
    int b = blockIdx.z, mt = blockIdx.y;
    int m0 = mt * 128, px0 = blockIdx.x * 128;
    int tid = threadIdx.x, lane = tid & 31, wid = tid >> 5;
    int wm = wid >> 2, wn = wid & 3;
    int g = lane >> 2, t = lane & 3;

    const __half* wsrc = g_wqkvh + (size_t)m0 * 256;
    const __half* xsrc = g_xh + ((size_t)b * 1024 + px0) * 256;

    auto load = [&](int st, int kc0) {
#pragma unroll
        for (int j = tid; j < 1024; j += 256) {
            int r = j >> 3, ch = j & 7;
            cpa16(&Asb[st][r * 72 + ch * 8], wsrc + (size_t)r * 256 + kc0 + ch * 8);
            cpa16(&Bsb[st][r * 72 + ch * 8], xsrc + (size_t)r * 256 + kc0 + ch * 8);
        }
    };

    float acc[4][4][4];
#pragma unroll
    for (int i = 0; i < 4; i++)
#pragma unroll
        for (int j = 0; j < 4; j++)
#pragma unroll
            for (int k = 0; k < 4; k++) acc[i][j][k] = 0.f;

    load(0, 0);
    CP_COMMIT();
    int st = 0;
#pragma unroll 1
    for (int ph = 0; ph < 4; ph++) {
        if (ph < 3) {
            load(st ^ 1, (ph + 1) * 64);
            CP_COMMIT();
            CP_WAIT(1);
        } else {
            CP_WAIT(0);
        }
        __syncthreads();
        mma_tile<4, 4, 4, 72>(Asb[st], Bsb[st], wm * 64, wn * 32, lane, acc);
        st ^= 1;
        __syncthreads();
    }

    float scale = (mt == 1) ? 0.25f * 1.44269504f : 1.0f;  // fold log2e into Q
#pragma unroll
    for (int mi = 0; mi < 4; mi++) {
        int r0 = wm * 64 + mi * 16 + g;
        float b0v = bias[m0 + r0], b1v = bias[m0 + r0 + 8];
#pragma unroll
        for (int ni = 0; ni < 4; ni++) {
            int px = px0 + wn * 32 + ni * 8 + 2 * t;
            float v0 = (acc[mi][ni][0] + b0v) * scale;
            float v1 = (acc[mi][ni][1] + b0v) * scale;
            float v2 = (acc[mi][ni][2] + b1v) * scale;
            float v3 = (acc[mi][ni][3] + b1v) * scale;
            if (mt == 2) {
                *reinterpret_cast<__half2*>(&g_v[((size_t)b * 128 + r0) * 1024 + px]) =
                    __floats2half2_rn(v0, v1);
                *reinterpret_cast<__half2*>(&g_v[((size_t)b * 128 + r0 + 8) * 1024 + px]) =
                    __floats2half2_rn(v2, v3);
            } else {
                __half* base = (mt == 0 ? g_kT : g_qT) + ((size_t)b * 1024 + px) * 128;
                base[r0] = __float2half(v0);
                base[r0 + 8] = __float2half(v2);
                base[128 + r0] = __float2half(v1);
                base[128 + r0 + 8] = __float2half(v3);
            }
        }
    }
}

// ---------------- kernel 2: conv implicit GEMM (M=128 co, N px, K=9*256) ----------------
// block tile 128x64, 256 thr, warp 32x32; cp.async double buffer, 18 phases (9 taps x K128)
__global__ void __launch_bounds__(256) k_conv(const float* __restrict__ conv_b,
                                              float* __restrict__ out) {
    extern __shared__ __half dsm[];
    // stage: As 128x136, Bs 64x136
    __half* Asb[2] = {dsm, dsm + 26112};
    __half* Bsb[2] = {dsm + 17408, dsm + 26112 + 17408};
    int b = blockIdx.y;
    int px0 = blockIdx.x * 64;
    int tid = threadIdx.x, lane = tid & 31, wid = tid >> 5;
    int wm = wid >> 1, wn = wid & 1;
    int g = lane >> 2, t = lane & 3;

    const __half* xbase = g_xh + (size_t)b * 1024 * 256;

    auto load = [&](int st, int ph) {
        int p = ph >> 1, kc0 = (ph & 1) * 128;
        int dh = p / 3 - 1, dw = p % 3 - 1;
#pragma unroll
        for (int j = tid; j < 2048; j += 256) {
            int r = j >> 4, ch = j & 15;
            cpa16(&Asb[st][r * 136 + ch * 8],
                  g_wconvh + (size_t)r * 2304 + p * 256 + kc0 + ch * 8);
        }
#pragma unroll
        for (int j = tid; j < 1024; j += 256) {
            int r = j >> 4, ch = j & 15;
            int px = px0 + r;
            int hy = (px >> 5) + dh, wx = (px & 31) + dw;
            bool ok = (hy >= 0) & (hy < HH) & (wx >= 0) & (wx < WW);
            const __half* src = ok ? xbase + ((size_t)(hy * 32 + wx)) * 256 + kc0 + ch * 8
                                   : xbase;
            cpa16z(&Bsb[st][r * 136 + ch * 8], src, ok);
        }
    };

    float acc[2][4][4];
#pragma unroll
    for (int i = 0; i < 2; i++)
#pragma unroll
        for (int j = 0; j < 4; j++)
#pragma unroll
            for (int k = 0; k < 4; k++) acc[i][j][k] = 0.f;

    load(0, 0);
    CP_COMMIT();
    int st = 0;
#pragma unroll 1
    for (int ph = 0; ph < 18; ph++) {
        if (ph < 17) {
            load(st ^ 1, ph + 1);
            CP_COMMIT();
            CP_WAIT(1);
        } else {
            CP_WAIT(0);
        }
        __syncthreads();
        mma_tile<2, 4, 8, 136>(Asb[st], Bsb[st], wm * 32, wn * 32, lane, acc);
        st ^= 1;
        __syncthreads();
    }

#pragma unroll
    for (int mi = 0; mi < 2; mi++) {
        int r0 = wm * 32 + mi * 16 + g;
        float b0v = conv_b[r0], b1v = conv_b[r0 + 8];
#pragma unroll
        for (int ni = 0; ni < 4; ni++) {
            int px = px0 + wn * 32 + ni * 8 + 2 * t;
            *(float2*)&out[((size_t)b * 256 + r0) * 1024 + px] =
                make_float2(acc[mi][ni][0] + b0v, acc[mi][ni][1] + b0v);
            *(float2*)&out[((size_t)b * 256 + r0 + 8) * 1024 + px] =
                make_float2(acc[mi][ni][2] + b1v, acc[mi][ni][3] + b1v);
        }
    }
}

// ---------------- kernel 3: attention ----------------
// grid (4 i-tiles, 8 heads, 16 b), 256 thr; Q pre-scaled by log2e -> ex2.f16x2;
// rowsum via MMA against constant all-ones B fragment.
__global__ void __launch_bounds__(256, 2) k_attn() {
    extern __shared__ __half sm[];
    __half* ksh = sm;                 // [1024 j][24]
    __half* vsh = sm + 1024 * 24;     // [16 d][1032 j]
    int b = blockIdx.z, h = blockIdx.y;
    int i0 = blockIdx.x * 256;
    int tid = threadIdx.x, lane = tid & 31, wid = tid >> 5;
    int g = lane >> 2, t = lane & 3;
    int l7 = lane & 7, s1 = (lane >> 3) & 1, s2 = lane >> 4;

    {
        const __half* kg = g_kT + (size_t)b * 1024 * 128 + h * 16;
#pragma unroll
        for (int i = tid; i < 2048; i += 256) {
            int j = i >> 1, ch = i & 1;
            *(uint4*)&ksh[j * 24 + ch * 8] = *(const uint4*)&kg[(size_t)j * 128 + ch * 8];
        }
    }
    {
        const __half* vg = g_v + ((size_t)b * 128 + h * 16) * 1024;
#pragma unroll
        for (int i = tid; i < 2048; i += 256) {
            int d = i >> 7, jc = i & 127;
            *(uint4*)&vsh[d * 1032 + jc * 8] = *(const uint4*)&vg[(size_t)d * 1024 + jc * 8];
        }
    }

    unsigned qa[2][4];
    {
        const __half* qg = g_qT + ((size_t)b * 1024 + i0 + wid * 32) * 128 + h * 16;
#pragma unroll
        for (int mi = 0; mi < 2; mi++) {
            qa[mi][0] = ldu32(&qg[(size_t)(mi * 16 + g) * 128 + 2 * t]);
            qa[mi][1] = ldu32(&qg[(size_t)(mi * 16 + g + 8) * 128 + 2 * t]);
            qa[mi][2] = ldu32(&qg[(size_t)(mi * 16 + g) * 128 + 2 * t + 8]);
            qa[mi][3] = ldu32(&qg[(size_t)(mi * 16 + g + 8) * 128 + 2 * t + 8]);
        }
    }
    __syncthreads();

    float oacc[2][2][4], rsacc[2][4];
#pragma unroll
    for (int i = 0; i < 2; i++) {
#pragma unroll
        for (int j = 0; j < 2; j++)
#pragma unroll
            for (int k = 0; k < 4; k++) oacc[i][j][k] = 0.f;
#pragma unroll
        for (int k = 0; k < 4; k++) rsacc[i][k] = 0.f;
    }
    const unsigned onesb[2] = {0x3C003C00u, 0x3C003C00u};

#pragma unroll 1
    for (int jc = 0; jc < 32; jc++) {
        int j0 = jc * 32;
        unsigned kb[4][2];
        ldsm4(kb[0][0], kb[0][1], kb[1][0], kb[1][1],
              &ksh[(j0 + s2 * 8 + l7) * 24 + s1 * 8]);
        ldsm4(kb[2][0], kb[2][1], kb[3][0], kb[3][1],
              &ksh[(j0 + 16 + s2 * 8 + l7) * 24 + s1 * 8]);

        float s[2][4][4];
#pragma unroll
        for (int mi = 0; mi < 2; mi++)
#pragma unroll
            for (int ni = 0; ni < 4; ni++) {
#pragma unroll
                for (int k = 0; k < 4; k++) s[mi][ni][k] = 0.f;
                mma16816(s[mi][ni], qa[mi], kb[ni]);
            }
        // s is already in log2 domain -> ex2.f16x2 gives exp(), packed fp16
        unsigned pf[2][4][2];
#pragma unroll
        for (int mi = 0; mi < 2; mi++)
#pragma unroll
            for (int ni = 0; ni < 4; ni++) {
                pf[mi][ni][0] = ex2h2(packh2(s[mi][ni][0], s[mi][ni][1]));
                pf[mi][ni][1] = ex2h2(packh2(s[mi][ni][2], s[mi][ni][3]));
            }
#pragma unroll
        for (int ks = 0; ks < 2; ks++) {
            unsigned av[2][4];
#pragma unroll
            for (int mi = 0; mi < 2; mi++) {
                av[mi][0] = pf[mi][2 * ks][0];
                av[mi][1] = pf[mi][2 * ks][1];
                av[mi][2] = pf[mi][2 * ks + 1][0];
                av[mi][3] = pf[mi][2 * ks + 1][1];
            }
            unsigned vb[2][2];
            ldsm4(vb[0][0], vb[0][1], vb[1][0], vb[1][1],
                  &vsh[(s2 * 8 + l7) * 1032 + j0 + ks * 16 + s1 * 8]);
#pragma unroll
            for (int nd = 0; nd < 2; nd++)
#pragma unroll
                for (int mi = 0; mi < 2; mi++) mma16816(oacc[mi][nd], av[mi], vb[nd]);
#pragma unroll
            for (int mi = 0; mi < 2; mi++) mma16816(rsacc[mi], av[mi], onesb);
        }
    }

    __half* og = g_ah + ((size_t)b * 1024 + i0 + wid * 32) * 128 + h * 16;
#pragma unroll
    for (int mi = 0; mi < 2; mi++) {
        float inv0 = 1.0f / rsacc[mi][0];
        float inv1 = 1.0f / rsacc[mi][2];
#pragma unroll
        for (int nd = 0; nd < 2; nd++) {
            int col = nd * 8 + 2 * t;
            *reinterpret_cast<__half2*>(&og[(size_t)(mi * 16 + g) * 128 + col]) =
                __floats2half2_rn(oacc[mi][nd][0] * inv0, oacc[mi][nd][1] * inv0);
            *reinterpret_cast<__half2*>(&og[(size_t)(mi * 16 + g + 8) * 128 + col]) =
                __floats2half2_rn(oacc[mi][nd][2] * inv1, oacc[mi][nd][3] * inv1);
        }
    }
}

// ---------------- kernel 4: proj GEMM (M=128, N=1024, K=128) ----------------
__global__ void __launch_bounds__(256) k_proj(const float* __restrict__ proj_b,
                                              float* __restrict__ out) {
    __shared__ __half As[128 * 72];
    __shared__ __half Bs[64 * 72];
    int b = blockIdx.y;
    int px0 = blockIdx.x * 64;
    int tid = threadIdx.x, lane = tid & 31, wid = tid >> 5;
    int wm = wid >> 1, wn = wid & 1;
    int g = lane >> 2, t = lane & 3;

    float acc[2][4][4];
#pragma unroll
    for (int i = 0; i < 2; i++)
#pragma unroll
        for (int j = 0; j < 4; j++)
#pragma unroll
            for (int k = 0; k < 4; k++) acc[i][j][k] = 0.f;

#pragma unroll 1
    for (int ph = 0; ph < 2; ph++) {
        int kc0 = ph * 64;
        __syncthreads();
#pragma unroll
        for (int i = tid; i < 128 * 8; i += 256) {
            int r = i >> 3, ch = i & 7;
            *(uint4*)&As[r * 72 + ch * 8] =
                *(const uint4*)&g_wprojh[(size_t)r * 128 + kc0 + ch * 8];
        }
#pragma unroll
        for (int i = tid; i < 64 * 8; i += 256) {
            int r = i >> 3, ch = i & 7;
            *(uint4*)&Bs[r * 72 + ch * 8] =
                *(const uint4*)&g_ah[((size_t)b * 1024 + px0 + r) * 128 + kc0 + ch * 8];
        }
        __syncthreads();
        mma_tile<2, 4, 4, 72>(As, Bs, wm * 32, wn * 32, lane, acc);
    }

#pragma unroll
    for (int mi = 0; mi < 2; mi++) {
        int r0 = wm * 32 + mi * 16 + g;
        float b0v = proj_b[r0], b1v = proj_b[r0 + 8];
#pragma unroll
        for (int ni = 0; ni < 4; ni++) {
            int px = px0 + wn * 32 + ni * 8 + 2 * t;
            *(float2*)&out[((size_t)b * 256 + 128 + r0) * 1024 + px] =
                make_float2(acc[mi][ni][0] + b0v, acc[mi][ni][1] + b0v);
            *(float2*)&out[((size_t)b * 256 + 128 + r0 + 8) * 1024 + px] =
                make_float2(acc[mi][ni][2] + b1v, acc[mi][ni][3] + b1v);
        }
    }
}

// ---------------------------------------------------------------------------
extern "C" void kernel_launch(void* const* d_in, const int* in_sizes, int n_in,
                              void* d_out, int out_size) {
    const float* x      = (const float*)d_in[0];
    const float* conv_w = (const float*)d_in[1];
    const float* conv_b = (const float*)d_in[2];
    const float* qkv_w  = (const float*)d_in[3];
    const float* qkv_b  = (const float*)d_in[4];
    const float* proj_w = (const float*)d_in[5];
    const float* proj_b = (const float*)d_in[6];
    float* out = (float*)d_out;

    static const int QKV_SMEM  = 2 * (128 * 72 + 128 * 72) * 2;          // 73728
    static const int CONV_SMEM = 2 * (128 * 136 + 64 * 136) * 2;         // 104448
    static const int ATTN_SMEM = (1024 * 24 + 16 * 1032) * 2;            // 82176
    cudaFuncSetAttribute(k_qkv,  cudaFuncAttributeMaxDynamicSharedMemorySize, QKV_SMEM);
    cudaFuncSetAttribute(k_conv, cudaFuncAttributeMaxDynamicSharedMemorySize, CONV_SMEM);
    cudaFuncSetAttribute(k_attn, cudaFuncAttributeMaxDynamicSharedMemorySize, ATTN_SMEM);

    k_cvt_x<<<dim3(32, 8, NB), dim3(32, 8)>>>(x);
    k_cvt_w<<<1152, 256>>>(qkv_w, proj_w, conv_w);
    k_qkv<<<dim3(8, 3, NB), 256, QKV_SMEM>>>(qkv_b);
    k_conv<<<dim3(16, NB), 256, CONV_SMEM>>>(conv_b, out);
    k_attn<<<dim3(4, 8, NB), 256, ATTN_SMEM>>>();
    k_proj<<<dim3(16, NB), 256>>>(proj_b, out);
}

// round 4
// speedup vs baseline: 8.1867x; 1.0195x over previous
#include <cuda_runtime.h>
#include <cuda_fp16.h>
#include <cstdint>

#define HH 32
#define WW 32
#define HW 1024
#define NB 16

// ---------------- scratch (allocation-free) ----------------
__device__ __half g_xh[NB * 1024 * 256];     // x transposed [b][px][c]
__device__ __half g_wqkvh[384 * 256];        // [o][c]
__device__ __half g_wconvh[128 * 9 * 256];   // [co][p*256+ci]
__device__ __half g_wprojh[128 * 128];       // [o][c]
__device__ __half g_kT[NB * 1024 * 128];     // [b][px][d]
__device__ __half g_qT[NB * 1024 * 128];     // [b][px][d] (pre-scaled by 0.25*log2e)
__device__ __half g_v[NB * 128 * 1024];      // [b][d][px]
__device__ __half g_ah[NB * 1024 * 128];     // attn out [b][px][c]

// ---------------- helpers ----------------
__device__ __forceinline__ void mma16816(float c[4], const unsigned a[4], const unsigned b[2]) {
    asm volatile(
        "mma.sync.aligned.m16n8k16.row.col.f32.f16.f16.f32 "
        "{%0,%1,%2,%3}, {%4,%5,%6,%7}, {%8,%9}, {%0,%1,%2,%3};\n"
        : "+f"(c[0]), "+f"(c[1]), "+f"(c[2]), "+f"(c[3])
        : "r"(a[0]), "r"(a[1]), "r"(a[2]), "r"(a[3]), "r"(b[0]), "r"(b[1]));
}
__device__ __forceinline__ void ldsm4(unsigned& r0, unsigned& r1, unsigned& r2, unsigned& r3,
                                      const __half* p) {
    uint32_t a = (uint32_t)__cvta_generic_to_shared(p);
    asm volatile("ldmatrix.sync.aligned.m8n8.x4.shared.b16 {%0,%1,%2,%3},[%4];\n"
                 : "=r"(r0), "=r"(r1), "=r"(r2), "=r"(r3) : "r"(a));
}
__device__ __forceinline__ unsigned ldu32(const __half* p) {
    return *reinterpret_cast<const unsigned*>(p);
}
__device__ __forceinline__ unsigned packh2(float a, float b) {
    __half2 h = __floats2half2_rn(a, b);
    return *reinterpret_cast<unsigned*>(&h);
}
__device__ __forceinline__ unsigned ex2h2(unsigned x) {
    unsigned d;
    asm("ex2.approx.f16x2 %0,%1;" : "=r"(d) : "r"(x));
    return d;
}
__device__ __forceinline__ void cpa16(const __half* dst, const __half* src) {
    uint32_t d = (uint32_t)__cvta_generic_to_shared(dst);
    asm volatile("cp.async.cg.shared.global [%0],[%1],16;\n" :: "r"(d), "l"(src));
}
__device__ __forceinline__ void cpa16z(const __half* dst, const __half* src, bool ok) {
    uint32_t d = (uint32_t)__cvta_generic_to_shared(dst);
    int sz = ok ? 16 : 0;
    asm volatile("cp.async.cg.shared.global [%0],[%1],16,%2;\n" :: "r"(d), "l"(src), "r"(sz));
}
#define CP_COMMIT() asm volatile("cp.async.commit_group;\n" ::: "memory")
#define CP_WAIT(n)  asm volatile("cp.async.wait_group %0;\n" :: "n"(n) : "memory")

// Generic MMA tile: A/B K-major, row stride STR halves.
template <int MI, int NI, int KSTEPS, int STR>
__device__ __forceinline__ void mma_tile(const __half* As, const __half* Bs, int arow0,
                                         int brow0, int lane, float (&acc)[MI][NI][4]) {
    int l7 = lane & 7, s1 = (lane >> 3) & 1, s2 = lane >> 4;
#pragma unroll
    for (int ks = 0; ks < KSTEPS; ks++) {
        unsigned af[MI][4], bf[NI][2];
#pragma unroll
        for (int mi = 0; mi < MI; mi++)
            ldsm4(af[mi][0], af[mi][1], af[mi][2], af[mi][3],
                  &As[(arow0 + mi * 16 + s1 * 8 + l7) * STR + ks * 16 + s2 * 8]);
#pragma unroll
        for (int np = 0; np < NI / 2; np++)
            ldsm4(bf[2 * np][0], bf[2 * np][1], bf[2 * np + 1][0], bf[2 * np + 1][1],
                  &Bs[(brow0 + np * 16 + s2 * 8 + l7) * STR + ks * 16 + s1 * 8]);
#pragma unroll
        for (int mi = 0; mi < MI; mi++)
#pragma unroll
            for (int ni = 0; ni < NI; ni++) mma16816(acc[mi][ni], af[mi], bf[ni]);
    }
}

// ---------------- conversion kernels ----------------
__global__ void k_cvt_x(const float* __restrict__ x) {
    __shared__ float t[32][33];
    int b = blockIdx.z, c0 = blockIdx.y * 32, px0 = blockIdx.x * 32;
    int tx = threadIdx.x, ty = threadIdx.y;
#pragma unroll
    for (int yy = 0; yy < 4; yy++)
        t[ty + yy * 8][tx] = x[((size_t)b * 256 + c0 + ty + yy * 8) * HW + px0 + tx];
    __syncthreads();
#pragma unroll
    for (int yy = 0; yy < 4; yy++)
        g_xh[((size_t)b * 1024 + px0 + ty + yy * 8) * 256 + c0 + tx] =
            __float2half(t[tx][ty + yy * 8]);
}

__global__ void k_cvt_w(const float* __restrict__ qkv_w,
                        const float* __restrict__ proj_w,
                        const float* __restrict__ conv_w) {
    int i = blockIdx.x * 256 + threadIdx.x;
    if (i < 384 * 256) g_wqkvh[i] = __float2half(qkv_w[i]);
    if (i < 128 * 128) g_wprojh[i] = __float2half(proj_w[i]);
    if (i < 128 * 2304) {
        int co = i / 2304;
        int k = i - co * 2304;
        g_wconvh[i] = __float2half(conv_w[(size_t)k * 128 + co]);
    }
}

// ---------------- kernel 1: QKV GEMM (M=384, N=1024, K=256 per batch) ----------------
// block tile 128x128, 256 thr, warp 64x32; single-sync double-buffered pipeline
__global__ void __launch_bounds__(256) k_qkv(const float* __restrict__ bias) {
    extern __shared__ __half dsm[];
    __half* Asb[2] = {dsm, dsm + 18432};
    __half* Bsb[2] = {dsm + 9216, dsm + 18432 + 9216};
    int b = blockIdx.z, mt = blockIdx.y;
    int m0 = mt * 128, px0 = blockIdx.x * 128;
    int tid = threadIdx.x, lane = tid & 31, wid = tid >> 5;
    int wm = wid >> 2, wn = wid & 3;
    int g = lane >> 2, t = lane & 3;

    const __half* wsrc = g_wqkvh + (size_t)m0 * 256;
    const __half* xsrc = g_xh + ((size_t)b * 1024 + px0) * 256;

    auto load = [&](int st, int kc0) {
#pragma unroll
        for (int j = tid; j < 1024; j += 256) {
            int r = j >> 3, ch = j & 7;
            cpa16(&Asb[st][r * 72 + ch * 8], wsrc + (size_t)r * 256 + kc0 + ch * 8);
            cpa16(&Bsb[st][r * 72 + ch * 8], xsrc + (size_t)r * 256 + kc0 + ch * 8);
        }
    };

    float acc[4][4][4];
#pragma unroll
    for (int i = 0; i < 4; i++)
#pragma unroll
        for (int j = 0; j < 4; j++)
#pragma unroll
            for (int k = 0; k < 4; k++) acc[i][j][k] = 0.f;

    load(0, 0);
    CP_COMMIT();
    int st = 0;
#pragma unroll 1
    for (int ph = 0; ph < 4; ph++) {
        CP_WAIT(0);
        __syncthreads();
        if (ph < 3) {
            load(st ^ 1, (ph + 1) * 64);
            CP_COMMIT();
        }
        mma_tile<4, 4, 4, 72>(Asb[st], Bsb[st], wm * 64, wn * 32, lane, acc);
        st ^= 1;
    }

    float scale = (mt == 1) ? 0.25f * 1.44269504f : 1.0f;  // fold log2e into Q
#pragma unroll
    for (int mi = 0; mi < 4; mi++) {
        int r0 = wm * 64 + mi * 16 + g;
        float b0v = bias[m0 + r0], b1v = bias[m0 + r0 + 8];
#pragma unroll
        for (int ni = 0; ni < 4; ni++) {
            int px = px0 + wn * 32 + ni * 8 + 2 * t;
            float v0 = (acc[mi][ni][0] + b0v) * scale;
            float v1 = (acc[mi][ni][1] + b0v) * scale;
            float v2 = (acc[mi][ni][2] + b1v) * scale;
            float v3 = (acc[mi][ni][3] + b1v) * scale;
            if (mt == 2) {
                *reinterpret_cast<__half2*>(&g_v[((size_t)b * 128 + r0) * 1024 + px]) =
                    __floats2half2_rn(v0, v1);
                *reinterpret_cast<__half2*>(&g_v[((size_t)b * 128 + r0 + 8) * 1024 + px]) =
                    __floats2half2_rn(v2, v3);
            } else {
                __half* base = (mt == 0 ? g_kT : g_qT) + ((size_t)b * 1024 + px) * 128;
                base[r0] = __float2half(v0);
                base[r0 + 8] = __float2half(v2);
                base[128 + r0] = __float2half(v1);
                base[128 + r0 + 8] = __float2half(v3);
            }
        }
    }
}

// ---------------- kernel 2: conv implicit GEMM with halo x-reuse ----------------
// Block: 128 co x 64 px (2 image rows). B = full-K halo tile [4 rows][34 cols][256 c],
// loaded ONCE (zfill edges), cell stride 264 halves (ldmatrix conflict-free).
// A (weights) double-buffered per (tap, K64-chunk): 36 phases, 1 sync each.
__global__ void __launch_bounds__(256) k_conv(const float* __restrict__ conv_b,
                                              float* __restrict__ out) {
    extern __shared__ __half dsm[];
    __half* Bs = dsm;                                   // 136 cells * 264 = 35904 halves
    __half* Asb[2] = {dsm + 35904, dsm + 35904 + 9216}; // each 128*72
    int b = blockIdx.y;
    int px0 = blockIdx.x * 64;
    int py0 = px0 >> 5;  // base image row
    int tid = threadIdx.x, lane = tid & 31, wid = tid >> 5;
    int wm = wid >> 1, wn = wid & 1;
    int g = lane >> 2, t = lane & 3;
    int l7 = lane & 7, s1 = (lane >> 3) & 1, s2 = lane >> 4;

    const __half* xbase = g_xh + (size_t)b * 1024 * 256;

    // one-time halo B load: rows py0-1..py0+2, cols -1..32, full K=256
#pragma unroll 1
    for (int j = tid; j < 4352; j += 256) {
        int ch = j & 31;            // 16B chunk (8 halves) within cell
        int cell = j >> 5;          // 0..135
        int r = cell / 34, cc = cell - r * 34;
        int hy = py0 - 1 + r, wx = cc - 1;
        bool ok = (hy >= 0) & (hy < HH) & (wx >= 0) & (wx < WW);
        const __half* src = ok ? xbase + ((size_t)(hy * 32 + wx)) * 256 + ch * 8 : xbase;
        cpa16z(&Bs[cell * 264 + ch * 8], src, ok);
    }
    CP_COMMIT();

    auto loadA = [&](int st, int ph) {
        int p = ph >> 2, cq = ph & 3;
        const __half* wsrc = g_wconvh + p * 256 + cq * 64;
#pragma unroll
        for (int j = tid; j < 1024; j += 256) {
            int r = j >> 3, ch = j & 7;
            cpa16(&Asb[st][r * 72 + ch * 8], wsrc + (size_t)r * 2304 + ch * 8);
        }
    };

    float acc[2][4][4];
#pragma unroll
    for (int i = 0; i < 2; i++)
#pragma unroll
        for (int j = 0; j < 4; j++)
#pragma unroll
            for (int k = 0; k < 4; k++) acc[i][j][k] = 0.f;

    loadA(0, 0);
    CP_COMMIT();
    int st = 0;
#pragma unroll 1
    for (int ph = 0; ph < 36; ph++) {
        CP_WAIT(0);
        __syncthreads();
        if (ph < 35) {
            loadA(st ^ 1, ph + 1);
            CP_COMMIT();
        }
        int p = ph >> 2, cq = ph & 3;
        int dh = p / 3 - 1, dw = p % 3 - 1;
        const __half* As = Asb[st];
        // per-lane shifted halo cell addresses (ldmatrix row pointers are per-lane)
        int bcell[2];
#pragma unroll
        for (int np = 0; np < 2; np++) {
            int j = wn * 32 + np * 16 + s2 * 8 + l7;
            int crow = (j >> 5) + dh + 1;
            int ccol = (j & 31) + dw + 1;
            bcell[np] = (crow * 34 + ccol) * 264 + cq * 64 + s1 * 8;
        }
#pragma unroll
        for (int ks = 0; ks < 4; ks++) {
            unsigned af[2][4], bf[4][2];
#pragma unroll
            for (int mi = 0; mi < 2; mi++)
                ldsm4(af[mi][0], af[mi][1], af[mi][2], af[mi][3],
                      &As[(wm * 32 + mi * 16 + s1 * 8 + l7) * 72 + ks * 16 + s2 * 8]);
#pragma unroll
            for (int np = 0; np < 2; np++)
                ldsm4(bf[2 * np][0], bf[2 * np][1], bf[2 * np + 1][0], bf[2 * np + 1][1],
                      &Bs[bcell[np] + ks * 16]);
#pragma unroll
            for (int mi = 0; mi < 2; mi++)
#pragma unroll
                for (int ni = 0; ni < 4; ni++) mma16816(acc[mi][ni], af[mi], bf[ni]);
        }
        st ^= 1;
    }

#pragma unroll
    for (int mi = 0; mi < 2; mi++) {
        int r0 = wm * 32 + mi * 16 + g;
        float b0v = conv_b[r0], b1v = conv_b[r0 + 8];
#pragma unroll
        for (int ni = 0; ni < 4; ni++) {
            int px = px0 + wn * 32 + ni * 8 + 2 * t;
            *(float2*)&out[((size_t)b * 256 + r0) * 1024 + px] =
                make_float2(acc[mi][ni][0] + b0v, acc[mi][ni][1] + b0v);
            *(float2*)&out[((size_t)b * 256 + r0 + 8) * 1024 + px] =
                make_float2(acc[mi][ni][2] + b1v, acc[mi][ni][3] + b1v);
        }
    }
}

// ---------------- kernel 3: attention ----------------
__global__ void __launch_bounds__(256, 2) k_attn() {
    extern __shared__ __half sm[];
    __half* ksh = sm;                 // [1024 j][24]
    __half* vsh = sm + 1024 * 24;     // [16 d][1032 j]
    int b = blockIdx.z, h = blockIdx.y;
    int i0 = blockIdx.x * 256;
    int tid = threadIdx.x, lane = tid & 31, wid = tid >> 5;
    int g = lane >> 2, t = lane & 3;
    int l7 = lane & 7, s1 = (lane >> 3) & 1, s2 = lane >> 4;

    {
        const __half* kg = g_kT + (size_t)b * 1024 * 128 + h * 16;
#pragma unroll
        for (int i = tid; i < 2048; i += 256) {
            int j = i >> 1, ch = i & 1;
            *(uint4*)&ksh[j * 24 + ch * 8] = *(const uint4*)&kg[(size_t)j * 128 + ch * 8];
        }
    }
    {
        const __half* vg = g_v + ((size_t)b * 128 + h * 16) * 1024;
#pragma unroll
        for (int i = tid; i < 2048; i += 256) {
            int d = i >> 7, jc = i & 127;
            *(uint4*)&vsh[d * 1032 + jc * 8] = *(const uint4*)&vg[(size_t)d * 1024 + jc * 8];
        }
    }

    unsigned qa[2][4];
    {
        const __half* qg = g_qT + ((size_t)b * 1024 + i0 + wid * 32) * 128 + h * 16;
#pragma unroll
        for (int mi = 0; mi < 2; mi++) {
            qa[mi][0] = ldu32(&qg[(size_t)(mi * 16 + g) * 128 + 2 * t]);
            qa[mi][1] = ldu32(&qg[(size_t)(mi * 16 + g + 8) * 128 + 2 * t]);
            qa[mi][2] = ldu32(&qg[(size_t)(mi * 16 + g) * 128 + 2 * t + 8]);
            qa[mi][3] = ldu32(&qg[(size_t)(mi * 16 + g + 8) * 128 + 2 * t + 8]);
        }
    }
    __syncthreads();

    float oacc[2][2][4], rsacc[2][4];
#pragma unroll
    for (int i = 0; i < 2; i++) {
#pragma unroll
        for (int j = 0; j < 2; j++)
#pragma unroll
            for (int k = 0; k < 4; k++) oacc[i][j][k] = 0.f;
#pragma unroll
        for (int k = 0; k < 4; k++) rsacc[i][k] = 0.f;
    }
    const unsigned onesb[2] = {0x3C003C00u, 0x3C003C00u};

#pragma unroll 1
    for (int jc = 0; jc < 32; jc++) {
        int j0 = jc * 32;
        unsigned kb[4][2];
        ldsm4(kb[0][0], kb[0][1], kb[1][0], kb[1][1],
              &ksh[(j0 + s2 * 8 + l7) * 24 + s1 * 8]);
        ldsm4(kb[2][0], kb[2][1], kb[3][0], kb[3][1],
              &ksh[(j0 + 16 + s2 * 8 + l7) * 24 + s1 * 8]);

        float s[2][4][4];
#pragma unroll
        for (int mi = 0; mi < 2; mi++)
#pragma unroll
            for (int ni = 0; ni < 4; ni++) {
#pragma unroll
                for (int k = 0; k < 4; k++) s[mi][ni][k] = 0.f;
                mma16816(s[mi][ni], qa[mi], kb[ni]);
            }
        unsigned pf[2][4][2];
#pragma unroll
        for (int mi = 0; mi < 2; mi++)
#pragma unroll
            for (int ni = 0; ni < 4; ni++) {
                pf[mi][ni][0] = ex2h2(packh2(s[mi][ni][0], s[mi][ni][1]));
                pf[mi][ni][1] = ex2h2(packh2(s[mi][ni][2], s[mi][ni][3]));
            }
#pragma unroll
        for (int ks = 0; ks < 2; ks++) {
            unsigned av[2][4];
#pragma unroll
            for (int mi = 0; mi < 2; mi++) {
                av[mi][0] = pf[mi][2 * ks][0];
                av[mi][1] = pf[mi][2 * ks][1];
                av[mi][2] = pf[mi][2 * ks + 1][0];
                av[mi][3] = pf[mi][2 * ks + 1][1];
            }
            unsigned vb[2][2];
            ldsm4(vb[0][0], vb[0][1], vb[1][0], vb[1][1],
                  &vsh[(s2 * 8 + l7) * 1032 + j0 + ks * 16 + s1 * 8]);
#pragma unroll
            for (int nd = 0; nd < 2; nd++)
#pragma unroll
                for (int mi = 0; mi < 2; mi++) mma16816(oacc[mi][nd], av[mi], vb[nd]);
#pragma unroll
            for (int mi = 0; mi < 2; mi++) mma16816(rsacc[mi], av[mi], onesb);
        }
    }

    __half* og = g_ah + ((size_t)b * 1024 + i0 + wid * 32) * 128 + h * 16;
#pragma unroll
    for (int mi = 0; mi < 2; mi++) {
        float inv0 = 1.0f / rsacc[mi][0];
        float inv1 = 1.0f / rsacc[mi][2];
#pragma unroll
        for (int nd = 0; nd < 2; nd++) {
            int col = nd * 8 + 2 * t;
            *reinterpret_cast<__half2*>(&og[(size_t)(mi * 16 + g) * 128 + col]) =
                __floats2half2_rn(oacc[mi][nd][0] * inv0, oacc[mi][nd][1] * inv0);
            *reinterpret_cast<__half2*>(&og[(size_t)(mi * 16 + g + 8) * 128 + col]) =
                __floats2half2_rn(oacc[mi][nd][2] * inv1, oacc[mi][nd][3] * inv1);
        }
    }
}

// ---------------- kernel 4: proj GEMM (M=128, N=1024, K=128) ----------------
__global__ void __launch_bounds__(256) k_proj(const float* __restrict__ proj_b,
                                              float* __restrict__ out) {
    __shared__ __half As[128 * 72];
    __shared__ __half Bs[64 * 72];
    int b = blockIdx.y;
    int px0 = blockIdx.x * 64;
    int tid = threadIdx.x, lane = tid & 31, wid = tid >> 5;
    int wm = wid >> 1, wn = wid & 1;
    int g = lane >> 2, t = lane & 3;

    float acc[2][4][4];
#pragma unroll
    for (int i = 0; i < 2; i++)
#pragma unroll
        for (int j = 0; j < 4; j++)
#pragma unroll
            for (int k = 0; k < 4; k++) acc[i][j][k] = 0.f;

#pragma unroll 1
    for (int ph = 0; ph < 2; ph++) {
        int kc0 = ph * 64;
        __syncthreads();
#pragma unroll
        for (int i = tid; i < 128 * 8; i += 256) {
            int r = i >> 3, ch = i & 7;
            *(uint4*)&As[r * 72 + ch * 8] =
                *(const uint4*)&g_wprojh[(size_t)r * 128 + kc0 + ch * 8];
        }
#pragma unroll
        for (int i = tid; i < 64 * 8; i += 256) {
            int r = i >> 3, ch = i & 7;
            *(uint4*)&Bs[r * 72 + ch * 8] =
                *(const uint4*)&g_ah[((size_t)b * 1024 + px0 + r) * 128 + kc0 + ch * 8];
        }
        __syncthreads();
        mma_tile<2, 4, 4, 72>(As, Bs, wm * 32, wn * 32, lane, acc);
    }

#pragma unroll
    for (int mi = 0; mi < 2; mi++) {
        int r0 = wm * 32 + mi * 16 + g;
        float b0v = proj_b[r0], b1v = proj_b[r0 + 8];
#pragma unroll
        for (int ni = 0; ni < 4; ni++) {
            int px = px0 + wn * 32 + ni * 8 + 2 * t;
            *(float2*)&out[((size_t)b * 256 + 128 + r0) * 1024 + px] =
                make_float2(acc[mi][ni][0] + b0v, acc[mi][ni][1] + b0v);
            *(float2*)&out[((size_t)b * 256 + 128 + r0 + 8) * 1024 + px] =
                make_float2(acc[mi][ni][2] + b1v, acc[mi][ni][3] + b1v);
        }
    }
}

// ---------------------------------------------------------------------------
extern "C" void kernel_launch(void* const* d_in, const int* in_sizes, int n_in,
                              void* d_out, int out_size) {
    const float* x      = (const float*)d_in[0];
    const float* conv_w = (const float*)d_in[1];
    const float* conv_b = (const float*)d_in[2];
    const float* qkv_w  = (const float*)d_in[3];
    const float* qkv_b  = (const float*)d_in[4];
    const float* proj_w = (const float*)d_in[5];
    const float* proj_b = (const float*)d_in[6];
    float* out = (float*)d_out;

    static const int QKV_SMEM  = 2 * (128 * 72 + 128 * 72) * 2;   // 73728
    static const int CONV_SMEM = (35904 + 2 * 9216) * 2;          // 108672
    static const int ATTN_SMEM = (1024 * 24 + 16 * 1032) * 2;     // 82176
    cudaFuncSetAttribute(k_qkv,  cudaFuncAttributeMaxDynamicSharedMemorySize, QKV_SMEM);
    cudaFuncSetAttribute(k_conv, cudaFuncAttributeMaxDynamicSharedMemorySize, CONV_SMEM);
    cudaFuncSetAttribute(k_attn, cudaFuncAttributeMaxDynamicSharedMemorySize, ATTN_SMEM);

    k_cvt_x<<<dim3(32, 8, NB), dim3(32, 8)>>>(x);
    k_cvt_w<<<1152, 256>>>(qkv_w, proj_w, conv_w);
    k_qkv<<<dim3(8, 3, NB), 256, QKV_SMEM>>>(qkv_b);
    k_conv<<<dim3(16, NB), 256, CONV_SMEM>>>(conv_b, out);
    k_attn<<<dim3(4, 8, NB), 256, ATTN_SMEM>>>();
    k_proj<<<dim3(16, NB), 256>>>(proj_b, out);
}

// round 5
// speedup vs baseline: 8.6708x; 1.0591x over previous
#include <cuda_runtime.h>
#include <cuda_fp16.h>
#include <cstdint>

#define HH 32
#define WW 32
#define HW 1024
#define NB 16

// ---------------- scratch (allocation-free) ----------------
__device__ __half g_xh[NB * 1024 * 256];     // x transposed [b][px][c]
__device__ __half g_wqkvh[384 * 256];        // [o][c]
__device__ __half g_wconvh[128 * 9 * 256];   // [co][p*256+ci]
__device__ __half g_wprojh[128 * 128];       // [o][c]
__device__ __half g_kT[NB * 1024 * 128];     // [b][px][d]
__device__ __half g_qT[NB * 1024 * 128];     // [b][px][d] (pre-scaled by 0.25*log2e)
__device__ __half g_v[NB * 128 * 1024];      // [b][d][px]
__device__ __half g_ah[NB * 1024 * 128];     // attn out [b][px][c]

// ---------------- helpers ----------------
__device__ __forceinline__ void mma16816(float c[4], const unsigned a[4], const unsigned b[2]) {
    asm volatile(
        "mma.sync.aligned.m16n8k16.row.col.f32.f16.f16.f32 "
        "{%0,%1,%2,%3}, {%4,%5,%6,%7}, {%8,%9}, {%0,%1,%2,%3};\n"
        : "+f"(c[0]), "+f"(c[1]), "+f"(c[2]), "+f"(c[3])
        : "r"(a[0]), "r"(a[1]), "r"(a[2]), "r"(a[3]), "r"(b[0]), "r"(b[1]));
}
__device__ __forceinline__ void ldsm4(unsigned& r0, unsigned& r1, unsigned& r2, unsigned& r3,
                                      const __half* p) {
    uint32_t a = (uint32_t)__cvta_generic_to_shared(p);
    asm volatile("ldmatrix.sync.aligned.m8n8.x4.shared.b16 {%0,%1,%2,%3},[%4];\n"
                 : "=r"(r0), "=r"(r1), "=r"(r2), "=r"(r3) : "r"(a));
}
__device__ __forceinline__ unsigned ldu32(const __half* p) {
    return *reinterpret_cast<const unsigned*>(p);
}
__device__ __forceinline__ unsigned packh2(float a, float b) {
    __half2 h = __floats2half2_rn(a, b);
    return *reinterpret_cast<unsigned*>(&h);
}
__device__ __forceinline__ unsigned ex2h2(unsigned x) {
    unsigned d;
    asm("ex2.approx.f16x2 %0,%1;" : "=r"(d) : "r"(x));
    return d;
}
__device__ __forceinline__ void cpa16(const __half* dst, const __half* src) {
    uint32_t d = (uint32_t)__cvta_generic_to_shared(dst);
    asm volatile("cp.async.cg.shared.global [%0],[%1],16;\n" :: "r"(d), "l"(src));
}
__device__ __forceinline__ void cpa16z(const __half* dst, const __half* src, bool ok) {
    uint32_t d = (uint32_t)__cvta_generic_to_shared(dst);
    int sz = ok ? 16 : 0;
    asm volatile("cp.async.cg.shared.global [%0],[%1],16,%2;\n" :: "r"(d), "l"(src), "r"(sz));
}
#define CP_COMMIT() asm volatile("cp.async.commit_group;\n" ::: "memory")
#define CP_WAIT(n)  asm volatile("cp.async.wait_group %0;\n" :: "n"(n) : "memory")

// Generic MMA tile: A/B K-major, row stride STR halves.
template <int MI, int NI, int KSTEPS, int STR>
__device__ __forceinline__ void mma_tile(const __half* As, const __half* Bs, int arow0,
                                         int brow0, int lane, float (&acc)[MI][NI][4]) {
    int l7 = lane & 7, s1 = (lane >> 3) & 1, s2 = lane >> 4;
#pragma unroll
    for (int ks = 0; ks < KSTEPS; ks++) {
        unsigned af[MI][4], bf[NI][2];
#pragma unroll
        for (int mi = 0; mi < MI; mi++)
            ldsm4(af[mi][0], af[mi][1], af[mi][2], af[mi][3],
                  &As[(arow0 + mi * 16 + s1 * 8 + l7) * STR + ks * 16 + s2 * 8]);
#pragma unroll
        for (int np = 0; np < NI / 2; np++)
            ldsm4(bf[2 * np][0], bf[2 * np][1], bf[2 * np + 1][0], bf[2 * np + 1][1],
                  &Bs[(brow0 + np * 16 + s2 * 8 + l7) * STR + ks * 16 + s1 * 8]);
#pragma unroll
        for (int mi = 0; mi < MI; mi++)
#pragma unroll
            for (int ni = 0; ni < NI; ni++) mma16816(acc[mi][ni], af[mi], bf[ni]);
    }
}

// ---------------- conversion kernels ----------------
__global__ void k_cvt_x(const float* __restrict__ x) {
    __shared__ float t[32][33];
    int b = blockIdx.z, c0 = blockIdx.y * 32, px0 = blockIdx.x * 32;
    int tx = threadIdx.x, ty = threadIdx.y;
#pragma unroll
    for (int yy = 0; yy < 4; yy++)
        t[ty + yy * 8][tx] = x[((size_t)b * 256 + c0 + ty + yy * 8) * HW + px0 + tx];
    __syncthreads();
#pragma unroll
    for (int yy = 0; yy < 4; yy++)
        g_xh[((size_t)b * 1024 + px0 + ty + yy * 8) * 256 + c0 + tx] =
            __float2half(t[tx][ty + yy * 8]);
}

__global__ void k_cvt_w(const float* __restrict__ qkv_w,
                        const float* __restrict__ proj_w,
                        const float* __restrict__ conv_w) {
    int i = blockIdx.x * 256 + threadIdx.x;
    if (i < 384 * 256) g_wqkvh[i] = __float2half(qkv_w[i]);
    if (i < 128 * 128) g_wprojh[i] = __float2half(proj_w[i]);
    if (i < 128 * 2304) {
        int co = i / 2304;
        int k = i - co * 2304;
        g_wconvh[i] = __float2half(conv_w[(size_t)k * 128 + co]);
    }
}

// ---------------- kernel 1: QKV GEMM (M=384, N=1024, K=256 per batch) ----------------
__global__ void __launch_bounds__(256) k_qkv(const float* __restrict__ bias) {
    extern __shared__ __half dsm[];
    __half* Asb[2] = {dsm, dsm + 18432};
    __half* Bsb[2] = {dsm + 9216, dsm + 18432 + 9216};
    int b = blockIdx.z, mt = blockIdx.y;
    int m0 = mt * 128, px0 = blockIdx.x * 128;
    int tid = threadIdx.x, lane = tid & 31, wid = tid >> 5;
    int wm = wid >> 2, wn = wid & 3;
    int g = lane >> 2, t = lane & 3;

    const __half* wsrc = g_wqkvh + (size_t)m0 * 256;
    const __half* xsrc = g_xh + ((size_t)b * 1024 + px0) * 256;

    auto load = [&](int st, int kc0) {
#pragma unroll
        for (int j = tid; j < 1024; j += 256) {
            int r = j >> 3, ch = j & 7;
            cpa16(&Asb[st][r * 72 + ch * 8], wsrc + (size_t)r * 256 + kc0 + ch * 8);
            cpa16(&Bsb[st][r * 72 + ch * 8], xsrc + (size_t)r * 256 + kc0 + ch * 8);
        }
    };

    float acc[4][4][4];
#pragma unroll
    for (int i = 0; i < 4; i++)
#pragma unroll
        for (int j = 0; j < 4; j++)
#pragma unroll
            for (int k = 0; k < 4; k++) acc[i][j][k] = 0.f;

    load(0, 0);
    CP_COMMIT();
    int st = 0;
#pragma unroll 1
    for (int ph = 0; ph < 4; ph++) {
        CP_WAIT(0);
        __syncthreads();
        if (ph < 3) {
            load(st ^ 1, (ph + 1) * 64);
            CP_COMMIT();
        }
        mma_tile<4, 4, 4, 72>(Asb[st], Bsb[st], wm * 64, wn * 32, lane, acc);
        st ^= 1;
    }

    float scale = (mt == 1) ? 0.25f * 1.44269504f : 1.0f;  // fold log2e into Q
#pragma unroll
    for (int mi = 0; mi < 4; mi++) {
        int r0 = wm * 64 + mi * 16 + g;
        float b0v = bias[m0 + r0], b1v = bias[m0 + r0 + 8];
#pragma unroll
        for (int ni = 0; ni < 4; ni++) {
            int px = px0 + wn * 32 + ni * 8 + 2 * t;
            float v0 = (acc[mi][ni][0] + b0v) * scale;
            float v1 = (acc[mi][ni][1] + b0v) * scale;
            float v2 = (acc[mi][ni][2] + b1v) * scale;
            float v3 = (acc[mi][ni][3] + b1v) * scale;
            if (mt == 2) {
                *reinterpret_cast<__half2*>(&g_v[((size_t)b * 128 + r0) * 1024 + px]) =
                    __floats2half2_rn(v0, v1);
                *reinterpret_cast<__half2*>(&g_v[((size_t)b * 128 + r0 + 8) * 1024 + px]) =
                    __floats2half2_rn(v2, v3);
            } else {
                __half* base = (mt == 0 ? g_kT : g_qT) + ((size_t)b * 1024 + px) * 128;
                base[r0] = __float2half(v0);
                base[r0 + 8] = __float2half(v2);
                base[128 + r0] = __float2half(v1);
                base[128 + r0 + 8] = __float2half(v3);
            }
        }
    }
}

// ---------------- kernel 2: conv implicit GEMM with halo x-reuse ----------------
__global__ void __launch_bounds__(256) k_conv(const float* __restrict__ conv_b,
                                              float* __restrict__ out) {
    extern __shared__ __half dsm[];
    __half* Bs = dsm;                                   // 136 cells * 264 halves
    __half* Asb[2] = {dsm + 35904, dsm + 35904 + 9216}; // each 128*72
    int b = blockIdx.y;
    int px0 = blockIdx.x * 64;
    int py0 = px0 >> 5;
    int tid = threadIdx.x, lane = tid & 31, wid = tid >> 5;
    int wm = wid >> 1, wn = wid & 1;
    int g = lane >> 2, t = lane & 3;
    int l7 = lane & 7, s1 = (lane >> 3) & 1, s2 = lane >> 4;

    const __half* xbase = g_xh + (size_t)b * 1024 * 256;

#pragma unroll 1
    for (int j = tid; j < 4352; j += 256) {
        int ch = j & 31;
        int cell = j >> 5;
        int r = cell / 34, cc = cell - r * 34;
        int hy = py0 - 1 + r, wx = cc - 1;
        bool ok = (hy >= 0) & (hy < HH) & (wx >= 0) & (wx < WW);
        const __half* src = ok ? xbase + ((size_t)(hy * 32 + wx)) * 256 + ch * 8 : xbase;
        cpa16z(&Bs[cell * 264 + ch * 8], src, ok);
    }
    CP_COMMIT();

    auto loadA = [&](int st, int ph) {
        int p = ph >> 2, cq = ph & 3;
        const __half* wsrc = g_wconvh + p * 256 + cq * 64;
#pragma unroll
        for (int j = tid; j < 1024; j += 256) {
            int r = j >> 3, ch = j & 7;
            cpa16(&Asb[st][r * 72 + ch * 8], wsrc + (size_t)r * 2304 + ch * 8);
        }
    };

    float acc[2][4][4];
#pragma unroll
    for (int i = 0; i < 2; i++)
#pragma unroll
        for (int j = 0; j < 4; j++)
#pragma unroll
            for (int k = 0; k < 4; k++) acc[i][j][k] = 0.f;

    loadA(0, 0);
    CP_COMMIT();
    int st = 0;
#pragma unroll 1
    for (int ph = 0; ph < 36; ph++) {
        CP_WAIT(0);
        __syncthreads();
        if (ph < 35) {
            loadA(st ^ 1, ph + 1);
            CP_COMMIT();
        }
        int p = ph >> 2, cq = ph & 3;
        int dh = p / 3 - 1, dw = p % 3 - 1;
        const __half* As = Asb[st];
        int bcell[2];
#pragma unroll
        for (int np = 0; np < 2; np++) {
            int j = wn * 32 + np * 16 + s2 * 8 + l7;
            int crow = (j >> 5) + dh + 1;
            int ccol = (j & 31) + dw + 1;
            bcell[np] = (crow * 34 + ccol) * 264 + cq * 64 + s1 * 8;
        }
#pragma unroll
        for (int ks = 0; ks < 4; ks++) {
            unsigned af[2][4], bf[4][2];
#pragma unroll
            for (int mi = 0; mi < 2; mi++)
                ldsm4(af[mi][0], af[mi][1], af[mi][2], af[mi][3],
                      &As[(wm * 32 + mi * 16 + s1 * 8 + l7) * 72 + ks * 16 + s2 * 8]);
#pragma unroll
            for (int np = 0; np < 2; np++)
                ldsm4(bf[2 * np][0], bf[2 * np][1], bf[2 * np + 1][0], bf[2 * np + 1][1],
                      &Bs[bcell[np] + ks * 16]);
#pragma unroll
            for (int mi = 0; mi < 2; mi++)
#pragma unroll
                for (int ni = 0; ni < 4; ni++) mma16816(acc[mi][ni], af[mi], bf[ni]);
        }
        st ^= 1;
    }

#pragma unroll
    for (int mi = 0; mi < 2; mi++) {
        int r0 = wm * 32 + mi * 16 + g;
        float b0v = conv_b[r0], b1v = conv_b[r0 + 8];
#pragma unroll
        for (int ni = 0; ni < 4; ni++) {
            int px = px0 + wn * 32 + ni * 8 + 2 * t;
            *(float2*)&out[((size_t)b * 256 + r0) * 1024 + px] =
                make_float2(acc[mi][ni][0] + b0v, acc[mi][ni][1] + b0v);
            *(float2*)&out[((size_t)b * 256 + r0 + 8) * 1024 + px] =
                make_float2(acc[mi][ni][2] + b1v, acc[mi][ni][3] + b1v);
        }
    }
}

// ---------------- kernel 3: attention ----------------
__global__ void __launch_bounds__(256, 2) k_attn() {
    extern __shared__ __half sm[];
    __half* ksh = sm;                 // [1024 j][24]
    __half* vsh = sm + 1024 * 24;     // [16 d][1032 j]
    int b = blockIdx.z, h = blockIdx.y;
    int i0 = blockIdx.x * 256;
    int tid = threadIdx.x, lane = tid & 31, wid = tid >> 5;
    int g = lane >> 2, t = lane & 3;
    int l7 = lane & 7, s1 = (lane >> 3) & 1, s2 = lane >> 4;

    {
        const __half* kg = g_kT + (size_t)b * 1024 * 128 + h * 16;
#pragma unroll
        for (int i = tid; i < 2048; i += 256) {
            int j = i >> 1, ch = i & 1;
            *(uint4*)&ksh[j * 24 + ch * 8] = *(const uint4*)&kg[(size_t)j * 128 + ch * 8];
        }
    }
    {
        const __half* vg = g_v + ((size_t)b * 128 + h * 16) * 1024;
#pragma unroll
        for (int i = tid; i < 2048; i += 256) {
            int d = i >> 7, jc = i & 127;
            *(uint4*)&vsh[d * 1032 + jc * 8] = *(const uint4*)&vg[(size_t)d * 1024 + jc * 8];
        }
    }

    unsigned qa[2][4];
    {
        const __half* qg = g_qT + ((size_t)b * 1024 + i0 + wid * 32) * 128 + h * 16;
#pragma unroll
        for (int mi = 0; mi < 2; mi++) {
            qa[mi][0] = ldu32(&qg[(size_t)(mi * 16 + g) * 128 + 2 * t]);
            qa[mi][1] = ldu32(&qg[(size_t)(mi * 16 + g + 8) * 128 + 2 * t]);
            qa[mi][2] = ldu32(&qg[(size_t)(mi * 16 + g) * 128 + 2 * t + 8]);
            qa[mi][3] = ldu32(&qg[(size_t)(mi * 16 + g + 8) * 128 + 2 * t + 8]);
        }
    }
    __syncthreads();

    float oacc[2][2][4], rsacc[2][4];
#pragma unroll
    for (int i = 0; i < 2; i++) {
#pragma unroll
        for (int j = 0; j < 2; j++)
#pragma unroll
            for (int k = 0; k < 4; k++) oacc[i][j][k] = 0.f;
#pragma unroll
        for (int k = 0; k < 4; k++) rsacc[i][k] = 0.f;
    }
    const unsigned onesb[2] = {0x3C003C00u, 0x3C003C00u};

#pragma unroll 1
    for (int jc = 0; jc < 32; jc++) {
        int j0 = jc * 32;
        unsigned kb[4][2];
        ldsm4(kb[0][0], kb[0][1], kb[1][0], kb[1][1],
              &ksh[(j0 + s2 * 8 + l7) * 24 + s1 * 8]);
        ldsm4(kb[2][0], kb[2][1], kb[3][0], kb[3][1],
              &ksh[(j0 + 16 + s2 * 8 + l7) * 24 + s1 * 8]);

        float s[2][4][4];
#pragma unroll
        for (int mi = 0; mi < 2; mi++)
#pragma unroll
            for (int ni = 0; ni < 4; ni++) {
#pragma unroll
                for (int k = 0; k < 4; k++) s[mi][ni][k] = 0.f;
                mma16816(s[mi][ni], qa[mi], kb[ni]);
            }
        unsigned pf[2][4][2];
#pragma unroll
        for (int mi = 0; mi < 2; mi++)
#pragma unroll
            for (int ni = 0; ni < 4; ni++) {
                pf[mi][ni][0] = ex2h2(packh2(s[mi][ni][0], s[mi][ni][1]));
                pf[mi][ni][1] = ex2h2(packh2(s[mi][ni][2], s[mi][ni][3]));
            }
#pragma unroll
        for (int ks = 0; ks < 2; ks++) {
            unsigned av[2][4];
#pragma unroll
            for (int mi = 0; mi < 2; mi++) {
                av[mi][0] = pf[mi][2 * ks][0];
                av[mi][1] = pf[mi][2 * ks][1];
                av[mi][2] = pf[mi][2 * ks + 1][0];
                av[mi][3] = pf[mi][2 * ks + 1][1];
            }
            unsigned vb[2][2];
            ldsm4(vb[0][0], vb[0][1], vb[1][0], vb[1][1],
                  &vsh[(s2 * 8 + l7) * 1032 + j0 + ks * 16 + s1 * 8]);
#pragma unroll
            for (int nd = 0; nd < 2; nd++)
#pragma unroll
                for (int mi = 0; mi < 2; mi++) mma16816(oacc[mi][nd], av[mi], vb[nd]);
#pragma unroll
            for (int mi = 0; mi < 2; mi++) mma16816(rsacc[mi], av[mi], onesb);
        }
    }

    __half* og = g_ah + ((size_t)b * 1024 + i0 + wid * 32) * 128 + h * 16;
#pragma unroll
    for (int mi = 0; mi < 2; mi++) {
        float inv0 = 1.0f / rsacc[mi][0];
        float inv1 = 1.0f / rsacc[mi][2];
#pragma unroll
        for (int nd = 0; nd < 2; nd++) {
            int col = nd * 8 + 2 * t;
            *reinterpret_cast<__half2*>(&og[(size_t)(mi * 16 + g) * 128 + col]) =
                __floats2half2_rn(oacc[mi][nd][0] * inv0, oacc[mi][nd][1] * inv0);
            *reinterpret_cast<__half2*>(&og[(size_t)(mi * 16 + g + 8) * 128 + col]) =
                __floats2half2_rn(oacc[mi][nd][2] * inv1, oacc[mi][nd][3] * inv1);
        }
    }
}

// ---------------- kernel 4: proj GEMM (M=128, N=1024, K=128) ----------------
__global__ void __launch_bounds__(256) k_proj(const float* __restrict__ proj_b,
                                              float* __restrict__ out) {
    __shared__ __half As[128 * 72];
    __shared__ __half Bs[64 * 72];
    int b = blockIdx.y;
    int px0 = blockIdx.x * 64;
    int tid = threadIdx.x, lane = tid & 31, wid = tid >> 5;
    int wm = wid >> 1, wn = wid & 1;
    int g = lane >> 2, t = lane & 3;

    float acc[2][4][4];
#pragma unroll
    for (int i = 0; i < 2; i++)
#pragma unroll
        for (int j = 0; j < 4; j++)
#pragma unroll
            for (int k = 0; k < 4; k++) acc[i][j][k] = 0.f;

#pragma unroll 1
    for (int ph = 0; ph < 2; ph++) {
        int kc0 = ph * 64;
        __syncthreads();
#pragma unroll
        for (int i = tid; i < 128 * 8; i += 256) {
            int r = i >> 3, ch = i & 7;
            *(uint4*)&As[r * 72 + ch * 8] =
                *(const uint4*)&g_wprojh[(size_t)r * 128 + kc0 + ch * 8];
        }
#pragma unroll
        for (int i = tid; i < 64 * 8; i += 256) {
            int r = i >> 3, ch = i & 7;
            *(uint4*)&Bs[r * 72 + ch * 8] =
                *(const uint4*)&g_ah[((size_t)b * 1024 + px0 + r) * 128 + kc0 + ch * 8];
        }
        __syncthreads();
        mma_tile<2, 4, 4, 72>(As, Bs, wm * 32, wn * 32, lane, acc);
    }

#pragma unroll
    for (int mi = 0; mi < 2; mi++) {
        int r0 = wm * 32 + mi * 16 + g;
        float b0v = proj_b[r0], b1v = proj_b[r0 + 8];
#pragma unroll
        for (int ni = 0; ni < 4; ni++) {
            int px = px0 + wn * 32 + ni * 8 + 2 * t;
            *(float2*)&out[((size_t)b * 256 + 128 + r0) * 1024 + px] =
                make_float2(acc[mi][ni][0] + b0v, acc[mi][ni][1] + b0v);
            *(float2*)&out[((size_t)b * 256 + 128 + r0 + 8) * 1024 + px] =
                make_float2(acc[mi][ni][2] + b1v, acc[mi][ni][3] + b1v);
        }
    }
}

// ---------------------------------------------------------------------------
extern "C" void kernel_launch(void* const* d_in, const int* in_sizes, int n_in,
                              void* d_out, int out_size) {
    const float* x      = (const float*)d_in[0];
    const float* conv_w = (const float*)d_in[1];
    const float* conv_b = (const float*)d_in[2];
    const float* qkv_w  = (const float*)d_in[3];
    const float* qkv_b  = (const float*)d_in[4];
    const float* proj_w = (const float*)d_in[5];
    const float* proj_b = (const float*)d_in[6];
    float* out = (float*)d_out;

    static const int QKV_SMEM  = 2 * (128 * 72 + 128 * 72) * 2;   // 73728
    static const int CONV_SMEM = (35904 + 2 * 9216) * 2;          // 108672
    static const int ATTN_SMEM = (1024 * 24 + 16 * 1032) * 2;     // 82176
    cudaFuncSetAttribute(k_qkv,  cudaFuncAttributeMaxDynamicSharedMemorySize, QKV_SMEM);
    cudaFuncSetAttribute(k_conv, cudaFuncAttributeMaxDynamicSharedMemorySize, CONV_SMEM);
    cudaFuncSetAttribute(k_attn, cudaFuncAttributeMaxDynamicSharedMemorySize, ATTN_SMEM);

    // Side stream + fork/join events (host objects; created once, lazily).
    static cudaStream_t s_conv = nullptr;
    static cudaEvent_t ev_fork = nullptr, ev_join = nullptr;
    if (s_conv == nullptr) {
        cudaStreamCreateWithFlags(&s_conv, cudaStreamNonBlocking);
        cudaEventCreateWithFlags(&ev_fork, cudaEventDisableTiming);
        cudaEventCreateWithFlags(&ev_join, cudaEventDisableTiming);
    }

    // main stream: conversions (produce g_xh + all fp16 weights)
    k_cvt_x<<<dim3(32, 8, NB), dim3(32, 8)>>>(x);
    k_cvt_w<<<1152, 256>>>(qkv_w, proj_w, conv_w);

    // fork: conv branch (writes out[ch 0..128)) runs concurrently
    cudaEventRecord(ev_fork, 0);
    cudaStreamWaitEvent(s_conv, ev_fork, 0);
    k_conv<<<dim3(16, NB), 256, CONV_SMEM, s_conv>>>(conv_b, out);
    cudaEventRecord(ev_join, s_conv);

    // main stream: attention branch (writes out[ch 128..256))
    k_qkv<<<dim3(8, 3, NB), 256, QKV_SMEM>>>(qkv_b);
    k_attn<<<dim3(4, 8, NB), 256, ATTN_SMEM>>>();
    k_proj<<<dim3(16, NB), 256>>>(proj_b, out);

    // join
    cudaStreamWaitEvent(0, ev_join, 0);
}

// round 6
// speedup vs baseline: 8.7300x; 1.0068x over previous
#include <cuda_runtime.h>
#include <cuda_fp16.h>
#include <cstdint>

#define HH 32
#define WW 32
#define HW 1024
#define NB 16

// ---------------- scratch (allocation-free) ----------------
__device__ __half g_xh[NB * 1024 * 256];     // x transposed [b][px][c]
__device__ __half g_wqkvh[384 * 256];        // [o][c]
__device__ __half g_wconvh[128 * 9 * 256];   // [co][p*256+ci]
__device__ __half g_wprojh[128 * 128];       // [o][c]
__device__ __half g_kT[NB * 1024 * 128];     // [b][px][d]
__device__ __half g_qT[NB * 1024 * 128];     // [b][px][d] (pre-scaled by 0.25*log2e)
__device__ __half g_v[NB * 128 * 1024];      // [b][d][px]
__device__ __half g_ah[NB * 1024 * 128];     // attn out [b][px][c]

// ---------------- helpers ----------------
__device__ __forceinline__ void mma16816(float c[4], const unsigned a[4], const unsigned b[2]) {
    asm volatile(
        "mma.sync.aligned.m16n8k16.row.col.f32.f16.f16.f32 "
        "{%0,%1,%2,%3}, {%4,%5,%6,%7}, {%8,%9}, {%0,%1,%2,%3};\n"
        : "+f"(c[0]), "+f"(c[1]), "+f"(c[2]), "+f"(c[3])
        : "r"(a[0]), "r"(a[1]), "r"(a[2]), "r"(a[3]), "r"(b[0]), "r"(b[1]));
}
__device__ __forceinline__ void ldsm4(unsigned& r0, unsigned& r1, unsigned& r2, unsigned& r3,
                                      const __half* p) {
    uint32_t a = (uint32_t)__cvta_generic_to_shared(p);
    asm volatile("ldmatrix.sync.aligned.m8n8.x4.shared.b16 {%0,%1,%2,%3},[%4];\n"
                 : "=r"(r0), "=r"(r1), "=r"(r2), "=r"(r3) : "r"(a));
}
__device__ __forceinline__ unsigned ldu32(const __half* p) {
    return *reinterpret_cast<const unsigned*>(p);
}
__device__ __forceinline__ unsigned packh2(float a, float b) {
    __half2 h = __floats2half2_rn(a, b);
    return *reinterpret_cast<unsigned*>(&h);
}
__device__ __forceinline__ unsigned ex2h2(unsigned x) {
    unsigned d;
    asm("ex2.approx.f16x2 %0,%1;" : "=r"(d) : "r"(x));
    return d;
}
__device__ __forceinline__ void cpa16(const __half* dst, const __half* src) {
    uint32_t d = (uint32_t)__cvta_generic_to_shared(dst);
    asm volatile("cp.async.cg.shared.global [%0],[%1],16;\n" :: "r"(d), "l"(src));
}
__device__ __forceinline__ void cpa16z(const __half* dst, const __half* src, bool ok) {
    uint32_t d = (uint32_t)__cvta_generic_to_shared(dst);
    int sz = ok ? 16 : 0;
    asm volatile("cp.async.cg.shared.global [%0],[%1],16,%2;\n" :: "r"(d), "l"(src), "r"(sz));
}
#define CP_COMMIT() asm volatile("cp.async.commit_group;\n" ::: "memory")
#define CP_WAIT(n)  asm volatile("cp.async.wait_group %0;\n" :: "n"(n) : "memory")

// Generic MMA tile: A/B K-major, row stride STR halves.
template <int MI, int NI, int KSTEPS, int STR>
__device__ __forceinline__ void mma_tile(const __half* As, const __half* Bs, int arow0,
                                         int brow0, int lane, float (&acc)[MI][NI][4]) {
    int l7 = lane & 7, s1 = (lane >> 3) & 1, s2 = lane >> 4;
#pragma unroll
    for (int ks = 0; ks < KSTEPS; ks++) {
        unsigned af[MI][4], bf[NI][2];
#pragma unroll
        for (int mi = 0; mi < MI; mi++)
            ldsm4(af[mi][0], af[mi][1], af[mi][2], af[mi][3],
                  &As[(arow0 + mi * 16 + s1 * 8 + l7) * STR + ks * 16 + s2 * 8]);
#pragma unroll
        for (int np = 0; np < NI / 2; np++)
            ldsm4(bf[2 * np][0], bf[2 * np][1], bf[2 * np + 1][0], bf[2 * np + 1][1],
                  &Bs[(brow0 + np * 16 + s2 * 8 + l7) * STR + ks * 16 + s1 * 8]);
#pragma unroll
        for (int mi = 0; mi < MI; mi++)
#pragma unroll
            for (int ni = 0; ni < NI; ni++) mma16816(acc[mi][ni], af[mi], bf[ni]);
    }
}

// ---------------- conversion kernels ----------------
__global__ void k_cvt_x(const float* __restrict__ x) {
    __shared__ float t[32][33];
    int b = blockIdx.z, c0 = blockIdx.y * 32, px0 = blockIdx.x * 32;
    int tx = threadIdx.x, ty = threadIdx.y;
#pragma unroll
    for (int yy = 0; yy < 4; yy++)
        t[ty + yy * 8][tx] = x[((size_t)b * 256 + c0 + ty + yy * 8) * HW + px0 + tx];
    __syncthreads();
#pragma unroll
    for (int yy = 0; yy < 4; yy++)
        g_xh[((size_t)b * 1024 + px0 + ty + yy * 8) * 256 + c0 + tx] =
            __float2half(t[tx][ty + yy * 8]);
}

__global__ void k_cvt_w(const float* __restrict__ qkv_w,
                        const float* __restrict__ proj_w,
                        const float* __restrict__ conv_w) {
    int i = blockIdx.x * 256 + threadIdx.x;
    if (i < 384 * 256) g_wqkvh[i] = __float2half(qkv_w[i]);
    if (i < 128 * 128) g_wprojh[i] = __float2half(proj_w[i]);
    if (i < 128 * 2304) {
        int co = i / 2304;
        int k = i - co * 2304;
        g_wconvh[i] = __float2half(conv_w[(size_t)k * 128 + co]);
    }
}

// ---------------- kernel 1: QKV GEMM (M=384, N=1024, K=256 per batch) ----------------
__global__ void __launch_bounds__(256) k_qkv(const float* __restrict__ bias) {
    extern __shared__ __half dsm[];
    __half* Asb[2] = {dsm, dsm + 18432};
    __half* Bsb[2] = {dsm + 9216, dsm + 18432 + 9216};
    int b = blockIdx.z, mt = blockIdx.y;
    int m0 = mt * 128, px0 = blockIdx.x * 128;
    int tid = threadIdx.x, lane = tid & 31, wid = tid >> 5;
    int wm = wid >> 2, wn = wid & 3;
    int g = lane >> 2, t = lane & 3;

    const __half* wsrc = g_wqkvh + (size_t)m0 * 256;
    const __half* xsrc = g_xh + ((size_t)b * 1024 + px0) * 256;

    auto load = [&](int st, int kc0) {
#pragma unroll
        for (int j = tid; j < 1024; j += 256) {
            int r = j >> 3, ch = j & 7;
            cpa16(&Asb[st][r * 72 + ch * 8], wsrc + (size_t)r * 256 + kc0 + ch * 8);
            cpa16(&Bsb[st][r * 72 + ch * 8], xsrc + (size_t)r * 256 + kc0 + ch * 8);
        }
    };

    float acc[4][4][4];
#pragma unroll
    for (int i = 0; i < 4; i++)
#pragma unroll
        for (int j = 0; j < 4; j++)
#pragma unroll
            for (int k = 0; k < 4; k++) acc[i][j][k] = 0.f;

    load(0, 0);
    CP_COMMIT();
    int st = 0;
#pragma unroll 1
    for (int ph = 0; ph < 4; ph++) {
        CP_WAIT(0);
        __syncthreads();
        if (ph < 3) {
            load(st ^ 1, (ph + 1) * 64);
            CP_COMMIT();
        }
        mma_tile<4, 4, 4, 72>(Asb[st], Bsb[st], wm * 64, wn * 32, lane, acc);
        st ^= 1;
    }

    float scale = (mt == 1) ? 0.25f * 1.44269504f : 1.0f;  // fold log2e into Q
#pragma unroll
    for (int mi = 0; mi < 4; mi++) {
        int r0 = wm * 64 + mi * 16 + g;
        float b0v = bias[m0 + r0], b1v = bias[m0 + r0 + 8];
#pragma unroll
        for (int ni = 0; ni < 4; ni++) {
            int px = px0 + wn * 32 + ni * 8 + 2 * t;
            float v0 = (acc[mi][ni][0] + b0v) * scale;
            float v1 = (acc[mi][ni][1] + b0v) * scale;
            float v2 = (acc[mi][ni][2] + b1v) * scale;
            float v3 = (acc[mi][ni][3] + b1v) * scale;
            if (mt == 2) {
                *reinterpret_cast<__half2*>(&g_v[((size_t)b * 128 + r0) * 1024 + px]) =
                    __floats2half2_rn(v0, v1);
                *reinterpret_cast<__half2*>(&g_v[((size_t)b * 128 + r0 + 8) * 1024 + px]) =
                    __floats2half2_rn(v2, v3);
            } else {
                __half* base = (mt == 0 ? g_kT : g_qT) + ((size_t)b * 1024 + px) * 128;
                base[r0] = __float2half(v0);
                base[r0 + 8] = __float2half(v2);
                base[128 + r0] = __float2half(v1);
                base[128 + r0 + 8] = __float2half(v3);
            }
        }
    }
}

// ---------------- kernel 2: conv implicit GEMM with halo x-reuse ----------------
__global__ void __launch_bounds__(256) k_conv(const float* __restrict__ conv_b,
                                              float* __restrict__ out) {
    extern __shared__ __half dsm[];
    __half* Bs = dsm;                                   // 136 cells * 264 halves
    __half* Asb[2] = {dsm + 35904, dsm + 35904 + 9216}; // each 128*72
    int b = blockIdx.y;
    int px0 = blockIdx.x * 64;
    int py0 = px0 >> 5;
    int tid = threadIdx.x, lane = tid & 31, wid = tid >> 5;
    int wm = wid >> 1, wn = wid & 1;
    int g = lane >> 2, t = lane & 3;
    int l7 = lane & 7, s1 = (lane >> 3) & 1, s2 = lane >> 4;

    const __half* xbase = g_xh + (size_t)b * 1024 * 256;

#pragma unroll 1
    for (int j = tid; j < 4352; j += 256) {
        int ch = j & 31;
        int cell = j >> 5;
        int r = cell / 34, cc = cell - r * 34;
        int hy = py0 - 1 + r, wx = cc - 1;
        bool ok = (hy >= 0) & (hy < HH) & (wx >= 0) & (wx < WW);
        const __half* src = ok ? xbase + ((size_t)(hy * 32 + wx)) * 256 + ch * 8 : xbase;
        cpa16z(&Bs[cell * 264 + ch * 8], src, ok);
    }
    CP_COMMIT();

    auto loadA = [&](int st, int ph) {
        int p = ph >> 2, cq = ph & 3;
        const __half* wsrc = g_wconvh + p * 256 + cq * 64;
#pragma unroll
        for (int j = tid; j < 1024; j += 256) {
            int r = j >> 3, ch = j & 7;
            cpa16(&Asb[st][r * 72 + ch * 8], wsrc + (size_t)r * 2304 + ch * 8);
        }
    };

    float acc[2][4][4];
#pragma unroll
    for (int i = 0; i < 2; i++)
#pragma unroll
        for (int j = 0; j < 4; j++)
#pragma unroll
            for (int k = 0; k < 4; k++) acc[i][j][k] = 0.f;

    loadA(0, 0);
    CP_COMMIT();
    int st = 0;
#pragma unroll 1
    for (int ph = 0; ph < 36; ph++) {
        CP_WAIT(0);
        __syncthreads();
        if (ph < 35) {
            loadA(st ^ 1, ph + 1);
            CP_COMMIT();
        }
        int p = ph >> 2, cq = ph & 3;
        int dh = p / 3 - 1, dw = p % 3 - 1;
        const __half* As = Asb[st];
        int bcell[2];
#pragma unroll
        for (int np = 0; np < 2; np++) {
            int j = wn * 32 + np * 16 + s2 * 8 + l7;
            int crow = (j >> 5) + dh + 1;
            int ccol = (j & 31) + dw + 1;
            bcell[np] = (crow * 34 + ccol) * 264 + cq * 64 + s1 * 8;
        }
#pragma unroll
        for (int ks = 0; ks < 4; ks++) {
            unsigned af[2][4], bf[4][2];
#pragma unroll
            for (int mi = 0; mi < 2; mi++)
                ldsm4(af[mi][0], af[mi][1], af[mi][2], af[mi][3],
                      &As[(wm * 32 + mi * 16 + s1 * 8 + l7) * 72 + ks * 16 + s2 * 8]);
#pragma unroll
            for (int np = 0; np < 2; np++)
                ldsm4(bf[2 * np][0], bf[2 * np][1], bf[2 * np + 1][0], bf[2 * np + 1][1],
                      &Bs[bcell[np] + ks * 16]);
#pragma unroll
            for (int mi = 0; mi < 2; mi++)
#pragma unroll
                for (int ni = 0; ni < 4; ni++) mma16816(acc[mi][ni], af[mi], bf[ni]);
        }
        st ^= 1;
    }

#pragma unroll
    for (int mi = 0; mi < 2; mi++) {
        int r0 = wm * 32 + mi * 16 + g;
        float b0v = conv_b[r0], b1v = conv_b[r0 + 8];
#pragma unroll
        for (int ni = 0; ni < 4; ni++) {
            int px = px0 + wn * 32 + ni * 8 + 2 * t;
            *(float2*)&out[((size_t)b * 256 + r0) * 1024 + px] =
                make_float2(acc[mi][ni][0] + b0v, acc[mi][ni][1] + b0v);
            *(float2*)&out[((size_t)b * 256 + r0 + 8) * 1024 + px] =
                make_float2(acc[mi][ni][2] + b1v, acc[mi][ni][3] + b1v);
        }
    }
}

// ---------------- kernel 3: attention ----------------
__global__ void __launch_bounds__(256, 2) k_attn() {
    extern __shared__ __half sm[];
    __half* ksh = sm;                 // [1024 j][24]
    __half* vsh = sm + 1024 * 24;     // [16 d][1032 j]
    int b = blockIdx.z, h = blockIdx.y;
    int i0 = blockIdx.x * 256;
    int tid = threadIdx.x, lane = tid & 31, wid = tid >> 5;
    int g = lane >> 2, t = lane & 3;
    int l7 = lane & 7, s1 = (lane >> 3) & 1, s2 = lane >> 4;

    {
        const __half* kg = g_kT + (size_t)b * 1024 * 128 + h * 16;
#pragma unroll
        for (int i = tid; i < 2048; i += 256) {
            int j = i >> 1, ch = i & 1;
            *(uint4*)&ksh[j * 24 + ch * 8] = *(const uint4*)&kg[(size_t)j * 128 + ch * 8];
        }
    }
    {
        const __half* vg = g_v + ((size_t)b * 128 + h * 16) * 1024;
#pragma unroll
        for (int i = tid; i < 2048; i += 256) {
            int d = i >> 7, jc = i & 127;
            *(uint4*)&vsh[d * 1032 + jc * 8] = *(const uint4*)&vg[(size_t)d * 1024 + jc * 8];
        }
    }

    unsigned qa[2][4];
    {
        const __half* qg = g_qT + ((size_t)b * 1024 + i0 + wid * 32) * 128 + h * 16;
#pragma unroll
        for (int mi = 0; mi < 2; mi++) {
            qa[mi][0] = ldu32(&qg[(size_t)(mi * 16 + g) * 128 + 2 * t]);
            qa[mi][1] = ldu32(&qg[(size_t)(mi * 16 + g + 8) * 128 + 2 * t]);
            qa[mi][2] = ldu32(&qg[(size_t)(mi * 16 + g) * 128 + 2 * t + 8]);
            qa[mi][3] = ldu32(&qg[(size_t)(mi * 16 + g + 8) * 128 + 2 * t + 8]);
        }
    }
    __syncthreads();

    float oacc[2][2][4], rsacc[2][4];
#pragma unroll
    for (int i = 0; i < 2; i++) {
#pragma unroll
        for (int j = 0; j < 2; j++)
#pragma unroll
            for (int k = 0; k < 4; k++) oacc[i][j][k] = 0.f;
#pragma unroll
        for (int k = 0; k < 4; k++) rsacc[i][k] = 0.f;
    }
    const unsigned onesb[2] = {0x3C003C00u, 0x3C003C00u};

#pragma unroll 1
    for (int jc = 0; jc < 32; jc++) {
        int j0 = jc * 32;
        unsigned kb[4][2];
        ldsm4(kb[0][0], kb[0][1], kb[1][0], kb[1][1],
              &ksh[(j0 + s2 * 8 + l7) * 24 + s1 * 8]);
        ldsm4(kb[2][0], kb[2][1], kb[3][0], kb[3][1],
              &ksh[(j0 + 16 + s2 * 8 + l7) * 24 + s1 * 8]);

        float s[2][4][4];
#pragma unroll
        for (int mi = 0; mi < 2; mi++)
#pragma unroll
            for (int ni = 0; ni < 4; ni++) {
#pragma unroll
                for (int k = 0; k < 4; k++) s[mi][ni][k] = 0.f;
                mma16816(s[mi][ni], qa[mi], kb[ni]);
            }
        unsigned pf[2][4][2];
#pragma unroll
        for (int mi = 0; mi < 2; mi++)
#pragma unroll
            for (int ni = 0; ni < 4; ni++) {
                pf[mi][ni][0] = ex2h2(packh2(s[mi][ni][0], s[mi][ni][1]));
                pf[mi][ni][1] = ex2h2(packh2(s[mi][ni][2], s[mi][ni][3]));
            }
#pragma unroll
        for (int ks = 0; ks < 2; ks++) {
            unsigned av[2][4];
#pragma unroll
            for (int mi = 0; mi < 2; mi++) {
                av[mi][0] = pf[mi][2 * ks][0];
                av[mi][1] = pf[mi][2 * ks][1];
                av[mi][2] = pf[mi][2 * ks + 1][0];
                av[mi][3] = pf[mi][2 * ks + 1][1];
            }
            unsigned vb[2][2];
            ldsm4(vb[0][0], vb[0][1], vb[1][0], vb[1][1],
                  &vsh[(s2 * 8 + l7) * 1032 + j0 + ks * 16 + s1 * 8]);
#pragma unroll
            for (int nd = 0; nd < 2; nd++)
#pragma unroll
                for (int mi = 0; mi < 2; mi++) mma16816(oacc[mi][nd], av[mi], vb[nd]);
#pragma unroll
            for (int mi = 0; mi < 2; mi++) mma16816(rsacc[mi], av[mi], onesb);
        }
    }

    __half* og = g_ah + ((size_t)b * 1024 + i0 + wid * 32) * 128 + h * 16;
#pragma unroll
    for (int mi = 0; mi < 2; mi++) {
        float inv0 = 1.0f / rsacc[mi][0];
        float inv1 = 1.0f / rsacc[mi][2];
#pragma unroll
        for (int nd = 0; nd < 2; nd++) {
            int col = nd * 8 + 2 * t;
            *reinterpret_cast<__half2*>(&og[(size_t)(mi * 16 + g) * 128 + col]) =
                __floats2half2_rn(oacc[mi][nd][0] * inv0, oacc[mi][nd][1] * inv0);
            *reinterpret_cast<__half2*>(&og[(size_t)(mi * 16 + g + 8) * 128 + col]) =
                __floats2half2_rn(oacc[mi][nd][2] * inv1, oacc[mi][nd][3] * inv1);
        }
    }
}

// ---------------- kernel 4: proj GEMM (M=128, N=1024, K=128) ----------------
__global__ void __launch_bounds__(256) k_proj(const float* __restrict__ proj_b,
                                              float* __restrict__ out) {
    __shared__ __half As[128 * 72];
    __shared__ __half Bs[64 * 72];
    int b = blockIdx.y;
    int px0 = blockIdx.x * 64;
    int tid = threadIdx.x, lane = tid & 31, wid = tid >> 5;
    int wm = wid >> 1, wn = wid & 1;
    int g = lane >> 2, t = lane & 3;

    float acc[2][4][4];
#pragma unroll
    for (int i = 0; i < 2; i++)
#pragma unroll
        for (int j = 0; j < 4; j++)
#pragma unroll
            for (int k = 0; k < 4; k++) acc[i][j][k] = 0.f;

#pragma unroll 1
    for (int ph = 0; ph < 2; ph++) {
        int kc0 = ph * 64;
        __syncthreads();
#pragma unroll
        for (int i = tid; i < 128 * 8; i += 256) {
            int r = i >> 3, ch = i & 7;
            *(uint4*)&As[r * 72 + ch * 8] =
                *(const uint4*)&g_wprojh[(size_t)r * 128 + kc0 + ch * 8];
        }
#pragma unroll
        for (int i = tid; i < 64 * 8; i += 256) {
            int r = i >> 3, ch = i & 7;
            *(uint4*)&Bs[r * 72 + ch * 8] =
                *(const uint4*)&g_ah[((size_t)b * 1024 + px0 + r) * 128 + kc0 + ch * 8];
        }
        __syncthreads();
        mma_tile<2, 4, 4, 72>(As, Bs, wm * 32, wn * 32, lane, acc);
    }

#pragma unroll
    for (int mi = 0; mi < 2; mi++) {
        int r0 = wm * 32 + mi * 16 + g;
        float b0v = proj_b[r0], b1v = proj_b[r0 + 8];
#pragma unroll
        for (int ni = 0; ni < 4; ni++) {
            int px = px0 + wn * 32 + ni * 8 + 2 * t;
            *(float2*)&out[((size_t)b * 256 + 128 + r0) * 1024 + px] =
                make_float2(acc[mi][ni][0] + b0v, acc[mi][ni][1] + b0v);
            *(float2*)&out[((size_t)b * 256 + 128 + r0 + 8) * 1024 + px] =
                make_float2(acc[mi][ni][2] + b1v, acc[mi][ni][3] + b1v);
        }
    }
}

// ---------------------------------------------------------------------------
extern "C" void kernel_launch(void* const* d_in, const int* in_sizes, int n_in,
                              void* d_out, int out_size) {
    const float* x      = (const float*)d_in[0];
    const float* conv_w = (const float*)d_in[1];
    const float* conv_b = (const float*)d_in[2];
    const float* qkv_w  = (const float*)d_in[3];
    const float* qkv_b  = (const float*)d_in[4];
    const float* proj_w = (const float*)d_in[5];
    const float* proj_b = (const float*)d_in[6];
    float* out = (float*)d_out;

    static const int QKV_SMEM  = 2 * (128 * 72 + 128 * 72) * 2;   // 73728
    static const int CONV_SMEM = (35904 + 2 * 9216) * 2;          // 108672
    static const int ATTN_SMEM = (1024 * 24 + 16 * 1032) * 2;     // 82176
    cudaFuncSetAttribute(k_qkv,  cudaFuncAttributeMaxDynamicSharedMemorySize, QKV_SMEM);
    cudaFuncSetAttribute(k_conv, cudaFuncAttributeMaxDynamicSharedMemorySize, CONV_SMEM);
    cudaFuncSetAttribute(k_attn, cudaFuncAttributeMaxDynamicSharedMemorySize, ATTN_SMEM);

    // Side stream + fork/join events (host objects; created once, lazily).
    static cudaStream_t s_conv = nullptr;
    static cudaEvent_t ev_fork = nullptr, ev_join = nullptr;
    if (s_conv == nullptr) {
        cudaStreamCreateWithFlags(&s_conv, cudaStreamNonBlocking);
        cudaEventCreateWithFlags(&ev_fork, cudaEventDisableTiming);
        cudaEventCreateWithFlags(&ev_join, cudaEventDisableTiming);
    }

    // main stream: conversions (produce g_xh + all fp16 weights)
    k_cvt_x<<<dim3(32, 8, NB), dim3(32, 8)>>>(x);
    k_cvt_w<<<1152, 256>>>(qkv_w, proj_w, conv_w);

    // fork: conv branch (writes out[ch 0..128)) runs concurrently
    cudaEventRecord(ev_fork, 0);
    cudaStreamWaitEvent(s_conv, ev_fork, 0);
    k_conv<<<dim3(16, NB), 256, CONV_SMEM, s_conv>>>(conv_b, out);
    cudaEventRecord(ev_join, s_conv);

    // main stream: attention branch (writes out[ch 128..256))
    k_qkv<<<dim3(8, 3, NB), 256, QKV_SMEM>>>(qkv_b);
    k_attn<<<dim3(4, 8, NB), 256, ATTN_SMEM>>>();
    k_proj<<<dim3(16, NB), 256>>>(proj_b, out);

    // join
    cudaStreamWaitEvent(0, ev_join, 0);
}

// round 8
// speedup vs baseline: 8.9186x; 1.0216x over previous
#include <cuda_runtime.h>
#include <cuda_fp16.h>
#include <cstdint>

#define HH 32
#define WW 32
#define HW 1024
#define NB 16

// ---------------- scratch (allocation-free) ----------------
__device__ __half g_xh[NB * 1024 * 256];     // x transposed [b][px][c]
__device__ __half g_wqkvh[384 * 256];        // [o][c]
__device__ __half g_wconvh[128 * 9 * 256];   // [co][p*256+ci]
__device__ __half g_wprojh[128 * 128];       // [o][c]
__device__ __half g_kT[NB * 1024 * 128];     // [b][px][d]
__device__ __half g_qT[NB * 1024 * 128];     // [b][px][d] (pre-scaled by 0.25*log2e)
__device__ __half g_v[NB * 128 * 1024];      // [b][d][px]
__device__ __half g_ah[NB * 1024 * 128];     // attn out [b][px][c]

// ---------------- helpers ----------------
__device__ __forceinline__ void mma16816(float c[4], const unsigned a[4], const unsigned b[2]) {
    asm volatile(
        "mma.sync.aligned.m16n8k16.row.col.f32.f16.f16.f32 "
        "{%0,%1,%2,%3}, {%4,%5,%6,%7}, {%8,%9}, {%0,%1,%2,%3};\n"
        : "+f"(c[0]), "+f"(c[1]), "+f"(c[2]), "+f"(c[3])
        : "r"(a[0]), "r"(a[1]), "r"(a[2]), "r"(a[3]), "r"(b[0]), "r"(b[1]));
}
// fp16-accumulate variant: C/D are 2 packed-b32 regs {row g | row g+8} x {2t,2t+1}
__device__ __forceinline__ void mma16816h(unsigned c[2], const unsigned a[4],
                                          const unsigned b[2]) {
    asm volatile(
        "mma.sync.aligned.m16n8k16.row.col.f16.f16.f16.f16 "
        "{%0,%1}, {%2,%3,%4,%5}, {%6,%7}, {%0,%1};\n"
        : "+r"(c[0]), "+r"(c[1])
        : "r"(a[0]), "r"(a[1]), "r"(a[2]), "r"(a[3]), "r"(b[0]), "r"(b[1]));
}
__device__ __forceinline__ void ldsm4(unsigned& r0, unsigned& r1, unsigned& r2, unsigned& r3,
                                      const __half* p) {
    uint32_t a = (uint32_t)__cvta_generic_to_shared(p);
    asm volatile("ldmatrix.sync.aligned.m8n8.x4.shared.b16 {%0,%1,%2,%3},[%4];\n"
                 : "=r"(r0), "=r"(r1), "=r"(r2), "=r"(r3) : "r"(a));
}
__device__ __forceinline__ unsigned ldu32(const __half* p) {
    return *reinterpret_cast<const unsigned*>(p);
}
__device__ __forceinline__ unsigned ex2h2(unsigned x) {
    unsigned d;
    asm("ex2.approx.f16x2 %0,%1;" : "=r"(d) : "r"(x));
    return d;
}
__device__ __forceinline__ void cpa16(const __half* dst, const __half* src) {
    uint32_t d = (uint32_t)__cvta_generic_to_shared(dst);
    asm volatile("cp.async.cg.shared.global [%0],[%1],16;\n" :: "r"(d), "l"(src));
}
__device__ __forceinline__ void cpa16z(const __half* dst, const __half* src, bool ok) {
    uint32_t d = (uint32_t)__cvta_generic_to_shared(dst);
    int sz = ok ? 16 : 0;
    asm volatile("cp.async.cg.shared.global [%0],[%1],16,%2;\n" :: "r"(d), "l"(src), "r"(sz));
}
#define CP_COMMIT() asm volatile("cp.async.commit_group;\n" ::: "memory")
#define CP_WAIT(n)  asm volatile("cp.async.wait_group %0;\n" :: "n"(n) : "memory")

// Generic MMA tile: A/B K-major, row stride STR halves.
template <int MI, int NI, int KSTEPS, int STR>
__device__ __forceinline__ void mma_tile(const __half* As, const __half* Bs, int arow0,
                                         int brow0, int lane, float (&acc)[MI][NI][4]) {
    int l7 = lane & 7, s1 = (lane >> 3) & 1, s2 = lane >> 4;
#pragma unroll
    for (int ks = 0; ks < KSTEPS; ks++) {
        unsigned af[MI][4], bf[NI][2];
#pragma unroll
        for (int mi = 0; mi < MI; mi++)
            ldsm4(af[mi][0], af[mi][1], af[mi][2], af[mi][3],
                  &As[(arow0 + mi * 16 + s1 * 8 + l7) * STR + ks * 16 + s2 * 8]);
#pragma unroll
        for (int np = 0; np < NI / 2; np++)
            ldsm4(bf[2 * np][0], bf[2 * np][1], bf[2 * np + 1][0], bf[2 * np + 1][1],
                  &Bs[(brow0 + np * 16 + s2 * 8 + l7) * STR + ks * 16 + s1 * 8]);
#pragma unroll
        for (int mi = 0; mi < MI; mi++)
#pragma unroll
            for (int ni = 0; ni < NI; ni++) mma16816(acc[mi][ni], af[mi], bf[ni]);
    }
}

// ---------------- conversion kernels ----------------
__global__ void k_cvt_x(const float* __restrict__ x) {
    __shared__ float t[32][33];
    int b = blockIdx.z, c0 = blockIdx.y * 32, px0 = blockIdx.x * 32;
    int tx = threadIdx.x, ty = threadIdx.y;
#pragma unroll
    for (int yy = 0; yy < 4; yy++)
        t[ty + yy * 8][tx] = x[((size_t)b * 256 + c0 + ty + yy * 8) * HW + px0 + tx];
    __syncthreads();
#pragma unroll
    for (int yy = 0; yy < 4; yy++)
        g_xh[((size_t)b * 1024 + px0 + ty + yy * 8) * 256 + c0 + tx] =
            __float2half(t[tx][ty + yy * 8]);
}

__global__ void k_cvt_w(const float* __restrict__ qkv_w,
                        const float* __restrict__ proj_w,
                        const float* __restrict__ conv_w) {
    int i = blockIdx.x * 256 + threadIdx.x;
    if (i < 384 * 256) g_wqkvh[i] = __float2half(qkv_w[i]);
    if (i < 128 * 128) g_wprojh[i] = __float2half(proj_w[i]);
    if (i < 128 * 2304) {
        int co = i / 2304;
        int k = i - co * 2304;
        g_wconvh[i] = __float2half(conv_w[(size_t)k * 128 + co]);
    }
}

// ---------------- kernel 1: QKV GEMM (M=384, N=1024, K=256 per batch) ----------------
__global__ void __launch_bounds__(256) k_qkv(const float* __restrict__ bias) {
    extern __shared__ __half dsm[];
    __half* Asb[2] = {dsm, dsm + 18432};
    __half* Bsb[2] = {dsm + 9216, dsm + 18432 + 9216};
    int b = blockIdx.z, mt = blockIdx.y;
    int m0 = mt * 128, px0 = blockIdx.x * 128;
    int tid = threadIdx.x, lane = tid & 31, wid = tid >> 5;
    int wm = wid >> 2, wn = wid & 3;
    int g = lane >> 2, t = lane & 3;

    const __half* wsrc = g_wqkvh + (size_t)m0 * 256;
    const __half* xsrc = g_xh + ((size_t)b * 1024 + px0) * 256;

    auto load = [&](int st, int kc0) {
#pragma unroll
        for (int j = tid; j < 1024; j += 256) {
            int r = j >> 3, ch = j & 7;
            cpa16(&Asb[st][r * 72 + ch * 8], wsrc + (size_t)r * 256 + kc0 + ch * 8);
            cpa16(&Bsb[st][r * 72 + ch * 8], xsrc + (size_t)r * 256 + kc0 + ch * 8);
        }
    };

    float acc[4][4][4];
#pragma unroll
    for (int i = 0; i < 4; i++)
#pragma unroll
        for (int j = 0; j < 4; j++)
#pragma unroll
            for (int k = 0; k < 4; k++) acc[i][j][k] = 0.f;

    load(0, 0);
    CP_COMMIT();
    int st = 0;
#pragma unroll 1
    for (int ph = 0; ph < 4; ph++) {
        CP_WAIT(0);
        __syncthreads();
        if (ph < 3) {
            load(st ^ 1, (ph + 1) * 64);
            CP_COMMIT();
        }
        mma_tile<4, 4, 4, 72>(Asb[st], Bsb[st], wm * 64, wn * 32, lane, acc);
        st ^= 1;
    }

    // ---- staged epilogue: coalesced gmem writes via smem ----
    __syncthreads();  // A/B buffers dead, reuse as stage
    __half* stg = dsm;  // K/Q: [128 px][136 o-pad]; V: [128 o][136 px-pad]
    float scale = (mt == 1) ? 0.25f * 1.44269504f : 1.0f;  // fold log2e into Q
#pragma unroll
    for (int mi = 0; mi < 4; mi++) {
        int r0 = wm * 64 + mi * 16 + g;
        float b0v = bias[m0 + r0], b1v = bias[m0 + r0 + 8];
#pragma unroll
        for (int ni = 0; ni < 4; ni++) {
            int px = wn * 32 + ni * 8 + 2 * t;  // local 0..127
            float v0 = (acc[mi][ni][0] + b0v) * scale;
            float v1 = (acc[mi][ni][1] + b0v) * scale;
            float v2 = (acc[mi][ni][2] + b1v) * scale;
            float v3 = (acc[mi][ni][3] + b1v) * scale;
            if (mt == 2) {
                *(__half2*)&stg[r0 * 136 + px] = __floats2half2_rn(v0, v1);
                *(__half2*)&stg[(r0 + 8) * 136 + px] = __floats2half2_rn(v2, v3);
            } else {
                stg[px * 136 + r0] = __float2half(v0);
                stg[(px + 1) * 136 + r0] = __float2half(v1);
                stg[px * 136 + r0 + 8] = __float2half(v2);
                stg[(px + 1) * 136 + r0 + 8] = __float2half(v3);
            }
        }
    }
    __syncthreads();
    if (mt == 2) {
        __half* dst = g_v + (size_t)b * 128 * 1024 + px0;
#pragma unroll
        for (int i = tid; i < 2048; i += 256) {
            int o = i >> 4, ch = i & 15;
            *(uint4*)&dst[(size_t)o * 1024 + ch * 8] = *(uint4*)&stg[o * 136 + ch * 8];
        }
    } else {
        __half* dst = (mt ? g_qT : g_kT) + ((size_t)b * 1024 + px0) * 128;
#pragma unroll
        for (int i = tid; i < 2048; i += 256) {
            int p = i >> 4, ch = i & 15;
            *(uint4*)&dst[(size_t)p * 128 + ch * 8] = *(uint4*)&stg[p * 136 + ch * 8];
        }
    }
}

// ---------------- kernel 2: conv implicit GEMM with halo x-reuse (unchanged) ----------
__global__ void __launch_bounds__(256) k_conv(const float* __restrict__ conv_b,
                                              float* __restrict__ out) {
    extern __shared__ __half dsm[];
    __half* Bs = dsm;                                   // 136 cells * 264 halves
    __half* Asb[2] = {dsm + 35904, dsm + 35904 + 9216}; // each 128*72
    int b = blockIdx.y;
    int px0 = blockIdx.x * 64;
    int py0 = px0 >> 5;
    int tid = threadIdx.x, lane = tid & 31, wid = tid >> 5;
    int wm = wid >> 1, wn = wid & 1;
    int g = lane >> 2, t = lane & 3;
    int l7 = lane & 7, s1 = (lane >> 3) & 1, s2 = lane >> 4;

    const __half* xbase = g_xh + (size_t)b * 1024 * 256;

#pragma unroll 1
    for (int j = tid; j < 4352; j += 256) {
        int ch = j & 31;
        int cell = j >> 5;
        int r = cell / 34, cc = cell - r * 34;
        int hy = py0 - 1 + r, wx = cc - 1;
        bool ok = (hy >= 0) & (hy < HH) & (wx >= 0) & (wx < WW);
        const __half* src = ok ? xbase + ((size_t)(hy * 32 + wx)) * 256 + ch * 8 : xbase;
        cpa16z(&Bs[cell * 264 + ch * 8], src, ok);
    }
    CP_COMMIT();

    auto loadA = [&](int st, int ph) {
        int p = ph >> 2, cq = ph & 3;
        const __half* wsrc = g_wconvh + p * 256 + cq * 64;
#pragma unroll
        for (int j = tid; j < 1024; j += 256) {
            int r = j >> 3, ch = j & 7;
            cpa16(&Asb[st][r * 72 + ch * 8], wsrc + (size_t)r * 2304 + ch * 8);
        }
    };

    float acc[2][4][4];
#pragma unroll
    for (int i = 0; i < 2; i++)
#pragma unroll
        for (int j = 0; j < 4; j++)
#pragma unroll
            for (int k = 0; k < 4; k++) acc[i][j][k] = 0.f;

    loadA(0, 0);
    CP_COMMIT();
    int st = 0;
#pragma unroll 1
    for (int ph = 0; ph < 36; ph++) {
        CP_WAIT(0);
        __syncthreads();
        if (ph < 35) {
            loadA(st ^ 1, ph + 1);
            CP_COMMIT();
        }
        int p = ph >> 2, cq = ph & 3;
        int dh = p / 3 - 1, dw = p % 3 - 1;
        const __half* As = Asb[st];
        int bcell[2];
#pragma unroll
        for (int np = 0; np < 2; np++) {
            int j = wn * 32 + np * 16 + s2 * 8 + l7;
            int crow = (j >> 5) + dh + 1;
            int ccol = (j & 31) + dw + 1;
            bcell[np] = (crow * 34 + ccol) * 264 + cq * 64 + s1 * 8;
        }
#pragma unroll
        for (int ks = 0; ks < 4; ks++) {
            unsigned af[2][4], bf[4][2];
#pragma unroll
            for (int mi = 0; mi < 2; mi++)
                ldsm4(af[mi][0], af[mi][1], af[mi][2], af[mi][3],
                      &As[(wm * 32 + mi * 16 + s1 * 8 + l7) * 72 + ks * 16 + s2 * 8]);
#pragma unroll
            for (int np = 0; np < 2; np++)
                ldsm4(bf[2 * np][0], bf[2 * np][1], bf[2 * np + 1][0], bf[2 * np + 1][1],
                      &Bs[bcell[np] + ks * 16]);
#pragma unroll
            for (int mi = 0; mi < 2; mi++)
#pragma unroll
                for (int ni = 0; ni < 4; ni++) mma16816(acc[mi][ni], af[mi], bf[ni]);
        }
        st ^= 1;
    }

#pragma unroll
    for (int mi = 0; mi < 2; mi++) {
        int r0 = wm * 32 + mi * 16 + g;
        float b0v = conv_b[r0], b1v = conv_b[r0 + 8];
#pragma unroll
        for (int ni = 0; ni < 4; ni++) {
            int px = px0 + wn * 32 + ni * 8 + 2 * t;
            *(float2*)&out[((size_t)b * 256 + r0) * 1024 + px] =
                make_float2(acc[mi][ni][0] + b0v, acc[mi][ni][1] + b0v);
            *(float2*)&out[((size_t)b * 256 + r0 + 8) * 1024 + px] =
                make_float2(acc[mi][ni][2] + b1v, acc[mi][ni][3] + b1v);
        }
    }
}

// ---------------- kernel 3: attention (QK^T in fp16-acc, direct ex2) ----------------
__global__ void __launch_bounds__(256, 2) k_attn() {
    extern __shared__ __half sm[];
    __half* ksh = sm;                 // [1024 j][24]
    __half* vsh = sm + 1024 * 24;     // [16 d][1032 j]
    int b = blockIdx.z, h = blockIdx.y, i0 = blockIdx.x * 256;
    int tid = threadIdx.x, lane = tid & 31, wid = tid >> 5;
    int g = lane >> 2, t = lane & 3;
    int l7 = lane & 7, s1 = (lane >> 3) & 1, s2 = lane >> 4;

    const __half* kg = g_kT + (size_t)b * 1024 * 128 + h * 16;
#pragma unroll
    for (int i = tid; i < 2048; i += 256) {
        int j = i >> 1, ch = i & 1;
        *(uint4*)&ksh[j * 24 + ch * 8] = *(const uint4*)&kg[(size_t)j * 128 + ch * 8];
    }
    const __half* vg = g_v + ((size_t)b * 128 + h * 16) * 1024;
#pragma unroll
    for (int i = tid; i < 2048; i += 256) {
        int d = i >> 7, jc = i & 127;
        *(uint4*)&vsh[d * 1032 + jc * 8] = *(const uint4*)&vg[(size_t)d * 1024 + jc * 8];
    }
    unsigned qa[2][4];
    const __half* qg = g_qT + ((size_t)b * 1024 + i0 + wid * 32) * 128 + h * 16;
#pragma unroll
    for (int mi = 0; mi < 2; mi++) {
        qa[mi][0] = ldu32(&qg[(size_t)(mi * 16 + g) * 128 + 2 * t]);
        qa[mi][1] = ldu32(&qg[(size_t)(mi * 16 + g + 8) * 128 + 2 * t]);
        qa[mi][2] = ldu32(&qg[(size_t)(mi * 16 + g) * 128 + 2 * t + 8]);
        qa[mi][3] = ldu32(&qg[(size_t)(mi * 16 + g + 8) * 128 + 2 * t + 8]);
    }
    __syncthreads();

    float oacc[2][2][4], rsacc[2][4];
#pragma unroll
    for (int i = 0; i < 2; i++) {
#pragma unroll
        for (int j = 0; j < 2; j++)
#pragma unroll
            for (int k = 0; k < 4; k++) oacc[i][j][k] = 0.f;
#pragma unroll
        for (int k = 0; k < 4; k++) rsacc[i][k] = 0.f;
    }
    const unsigned onesb[2] = {0x3C003C00u, 0x3C003C00u};

#pragma unroll 1
    for (int jc = 0; jc < 32; jc++) {
        int j0 = jc * 32;
        unsigned kb[4][2];
        ldsm4(kb[0][0], kb[0][1], kb[1][0], kb[1][1],
              &ksh[(j0 + s2 * 8 + l7) * 24 + s1 * 8]);
        ldsm4(kb[2][0], kb[2][1], kb[3][0], kb[3][1],
              &ksh[(j0 + 16 + s2 * 8 + l7) * 24 + s1 * 8]);

        // S = QK^T in fp16-acc (log2 domain) -> ex2 directly on packed halves
        unsigned pf[2][4][2];
#pragma unroll
        for (int mi = 0; mi < 2; mi++)
#pragma unroll
            for (int ni = 0; ni < 4; ni++) {
                unsigned sh[2] = {0u, 0u};
                mma16816h(sh, qa[mi], kb[ni]);
                pf[mi][ni][0] = ex2h2(sh[0]);
                pf[mi][ni][1] = ex2h2(sh[1]);
            }
#pragma unroll
        for (int ks = 0; ks < 2; ks++) {
            unsigned av[2][4];
#pragma unroll
            for (int mi = 0; mi < 2; mi++) {
                av[mi][0] = pf[mi][2 * ks][0];
                av[mi][1] = pf[mi][2 * ks][1];
                av[mi][2] = pf[mi][2 * ks + 1][0];
                av[mi][3] = pf[mi][2 * ks + 1][1];
            }
            unsigned vb[2][2];
            ldsm4(vb[0][0], vb[0][1], vb[1][0], vb[1][1],
                  &vsh[(s2 * 8 + l7) * 1032 + j0 + ks * 16 + s1 * 8]);
#pragma unroll
            for (int nd = 0; nd < 2; nd++)
#pragma unroll
                for (int mi = 0; mi < 2; mi++) mma16816(oacc[mi][nd], av[mi], vb[nd]);
#pragma unroll
            for (int mi = 0; mi < 2; mi++) mma16816(rsacc[mi], av[mi], onesb);
        }
    }

    // ---- staged epilogue: [256 px][16 c] tile in dead ksh, then 16B writes ----
    __syncthreads();
    __half* stg = ksh;
#pragma unroll
    for (int mi = 0; mi < 2; mi++) {
        float inv0 = 1.0f / rsacc[mi][0], inv1 = 1.0f / rsacc[mi][2];
        int lpx = wid * 32 + mi * 16 + g;
#pragma unroll
        for (int nd = 0; nd < 2; nd++) {
            int col = nd * 8 + 2 * t;
            *(__half2*)&stg[lpx * 16 + col] =
                __floats2half2_rn(oacc[mi][nd][0] * inv0, oacc[mi][nd][1] * inv0);
            *(__half2*)&stg[(lpx + 8) * 16 + col] =
                __floats2half2_rn(oacc[mi][nd][2] * inv1, oacc[mi][nd][3] * inv1);
        }
    }
    __syncthreads();
    {
        int px = tid;
        __half* og = g_ah + ((size_t)b * 1024 + i0 + px) * 128 + h * 16;
        *(uint4*)og = *(uint4*)&stg[px * 16];
        *(uint4*)(og + 8) = *(uint4*)&stg[px * 16 + 8];
    }
}

// ---------------- kernel 4: proj GEMM (unchanged) ----------------
__global__ void __launch_bounds__(256) k_proj(const float* __restrict__ proj_b,
                                              float* __restrict__ out) {
    __shared__ __half As[128 * 72];
    __shared__ __half Bs[64 * 72];
    int b = blockIdx.y, px0 = blockIdx.x * 64;
    int tid = threadIdx.x, lane = tid & 31, wid = tid >> 5;
    int wm = wid >> 1, wn = wid & 1;
    int g = lane >> 2, t = lane & 3;
    float acc[2][4][4];
#pragma unroll
    for (int i = 0; i < 2; i++)
#pragma unroll
        for (int j = 0; j < 4; j++)
#pragma unroll
            for (int k = 0; k < 4; k++) acc[i][j][k] = 0.f;
#pragma unroll 1
    for (int ph = 0; ph < 2; ph++) {
        int kc0 = ph * 64;
        __syncthreads();
#pragma unroll
        for (int i = tid; i < 1024; i += 256) {
            int r = i >> 3, ch = i & 7;
            *(uint4*)&As[r * 72 + ch * 8] =
                *(const uint4*)&g_wprojh[(size_t)r * 128 + kc0 + ch * 8];
        }
#pragma unroll
        for (int i = tid; i < 512; i += 256) {
            int r = i >> 3, ch = i & 7;
            *(uint4*)&Bs[r * 72 + ch * 8] =
                *(const uint4*)&g_ah[((size_t)b * 1024 + px0 + r) * 128 + kc0 + ch * 8];
        }
        __syncthreads();
        mma_tile<2, 4, 4, 72>(As, Bs, wm * 32, wn * 32, lane, acc);
    }
#pragma unroll
    for (int mi = 0; mi < 2; mi++) {
        int r0 = wm * 32 + mi * 16 + g;
        float b0v = proj_b[r0], b1v = proj_b[r0 + 8];
#pragma unroll
        for (int ni = 0; ni < 4; ni++) {
            int px = px0 + wn * 32 + ni * 8 + 2 * t;
            *(float2*)&out[((size_t)b * 256 + 128 + r0) * 1024 + px] =
                make_float2(acc[mi][ni][0] + b0v, acc[mi][ni][1] + b0v);
            *(float2*)&out[((size_t)b * 256 + 128 + r0 + 8) * 1024 + px] =
                make_float2(acc[mi][ni][2] + b1v, acc[mi][ni][3] + b1v);
        }
    }
}

// ---------------------------------------------------------------------------
extern "C" void kernel_launch(void* const* d_in, const int* in_sizes, int n_in,
                              void* d_out, int out_size) {
    const float* x      = (const float*)d_in[0];
    const float* conv_w = (const float*)d_in[1];
    const float* conv_b = (const float*)d_in[2];
    const float* qkv_w  = (const float*)d_in[3];
    const float* qkv_b  = (const float*)d_in[4];
    const float* proj_w = (const float*)d_in[5];
    const float* proj_b = (const float*)d_in[6];
    float* out = (float*)d_out;

    static const int QKV_SMEM  = 2 * (128 * 72 + 128 * 72) * 2;   // 73728
    static const int CONV_SMEM = (35904 + 2 * 9216) * 2;          // 108672
    static const int ATTN_SMEM = (1024 * 24 + 16 * 1032) * 2;     // 82176
    cudaFuncSetAttribute(k_qkv,  cudaFuncAttributeMaxDynamicSharedMemorySize, QKV_SMEM);
    cudaFuncSetAttribute(k_conv, cudaFuncAttributeMaxDynamicSharedMemorySize, CONV_SMEM);
    cudaFuncSetAttribute(k_attn, cudaFuncAttributeMaxDynamicSharedMemorySize, ATTN_SMEM);

    static cudaStream_t s_conv = nullptr;
    static cudaEvent_t ev_fork = nullptr, ev_join = nullptr;
    if (s_conv == nullptr) {
        cudaStreamCreateWithFlags(&s_conv, cudaStreamNonBlocking);
        cudaEventCreateWithFlags(&ev_fork, cudaEventDisableTiming);
        cudaEventCreateWithFlags(&ev_join, cudaEventDisableTiming);
    }

    k_cvt_x<<<dim3(32, 8, NB), dim3(32, 8)>>>(x);
    k_cvt_w<<<1152, 256>>>(qkv_w, proj_w, conv_w);

    cudaEventRecord(ev_fork, 0);
    cudaStreamWaitEvent(s_conv, ev_fork, 0);
    k_conv<<<dim3(16, NB), 256, CONV_SMEM, s_conv>>>(conv_b, out);
    cudaEventRecord(ev_join, s_conv);

    k_qkv<<<dim3(8, 3, NB), 256, QKV_SMEM>>>(qkv_b);
    k_attn<<<dim3(4, 8, NB), 256, ATTN_SMEM>>>();
    k_proj<<<dim3(16, NB), 256>>>(proj_b, out);

    cudaStreamWaitEvent(0, ev_join, 0);
}